// round 1
// baseline (speedup 1.0000x reference)
#include <cuda_runtime.h>

// Problem constants (fixed by reference): B=8, N=1024, C=1024, H=16, D=64
#define BB 8
#define NN 1024
#define CC 1024
#define HH 16
#define DD 64
#define SCALE 0.125f   // 64^-0.5

// Scratch: q,k,v,attn_out in [B,H,N,D] layout (bh = b*16+h)
__device__ float g_q[BB*HH*NN*DD];
__device__ float g_k[BB*HH*NN*DD];
__device__ float g_v[BB*HH*NN*DD];
__device__ float g_o[BB*HH*NN*DD];

// ---------------------------------------------------------------------------
// GEMM 1: qkv = x @ w_in^T + b_in ; scatter into g_q/g_k/g_v [B,H,N,D]
// C tile 128x64, K-step 16, 256 threads, 8x4 microtile.
// ---------------------------------------------------------------------------
__global__ void __launch_bounds__(256) gemm_qkv_kernel(
        const float* __restrict__ x, const float* __restrict__ w,
        const float* __restrict__ bias) {
    __shared__ float As[16][132];   // k-major A tile (128 rows), padded
    __shared__ float Bs[16][68];    // k-major B tile (64 cols), padded

    const int tid = threadIdx.x;
    const int tx = tid & 15, ty = tid >> 4;
    const int row0 = blockIdx.y * 128;
    const int col0 = blockIdx.x * 64;

    float acc[8][4];
#pragma unroll
    for (int i = 0; i < 8; i++)
#pragma unroll
        for (int j = 0; j < 4; j++) acc[i][j] = 0.f;

    const int kk = tid & 15;
    const int rr = tid >> 4;

    for (int k0 = 0; k0 < 1024; k0 += 16) {
#pragma unroll
        for (int p = 0; p < 8; p++) {
            int r = rr + p * 16;
            As[kk][r] = x[(row0 + r) * 1024 + k0 + kk];
        }
#pragma unroll
        for (int p = 0; p < 4; p++) {
            int c = rr + p * 16;
            Bs[kk][c] = w[(col0 + c) * 1024 + k0 + kk];
        }
        __syncthreads();
#pragma unroll
        for (int q = 0; q < 16; q++) {
            float4 a0 = *(const float4*)&As[q][ty * 8];
            float4 a1 = *(const float4*)&As[q][ty * 8 + 4];
            float4 bq = *(const float4*)&Bs[q][tx * 4];
            float a[8] = {a0.x, a0.y, a0.z, a0.w, a1.x, a1.y, a1.z, a1.w};
            float bv[4] = {bq.x, bq.y, bq.z, bq.w};
#pragma unroll
            for (int i = 0; i < 8; i++)
#pragma unroll
                for (int j = 0; j < 4; j++)
                    acc[i][j] = fmaf(a[i], bv[j], acc[i][j]);
        }
        __syncthreads();
    }

    // epilogue: bias + scatter to [B,H,N,D]
#pragma unroll
    for (int i = 0; i < 8; i++) {
        int row = row0 + ty * 8 + i;
        int b = row >> 10, n = row & 1023;
#pragma unroll
        for (int j = 0; j < 4; j++) {
            int col = col0 + tx * 4 + j;
            float v = acc[i][j] + bias[col];
            int sec = col >> 10;       // 0:q 1:k 2:v
            int cc = col & 1023;
            int h = cc >> 6, d = cc & 63;
            float* dst = (sec == 0) ? g_q : (sec == 1) ? g_k : g_v;
            dst[((b * 16 + h) * 1024 + n) * 64 + d] = v;
        }
    }
}

// ---------------------------------------------------------------------------
// GEMM 2: out = attn_out @ w_out^T + b_out, reading g_o [B,H,N,D] as [B*N, C]
// ---------------------------------------------------------------------------
__global__ void __launch_bounds__(256) gemm_out_kernel(
        const float* __restrict__ w, const float* __restrict__ bias,
        float* __restrict__ out) {
    __shared__ float As[16][132];
    __shared__ float Bs[16][68];

    const int tid = threadIdx.x;
    const int tx = tid & 15, ty = tid >> 4;
    const int row0 = blockIdx.y * 128;
    const int col0 = blockIdx.x * 64;

    float acc[8][4];
#pragma unroll
    for (int i = 0; i < 8; i++)
#pragma unroll
        for (int j = 0; j < 4; j++) acc[i][j] = 0.f;

    const int kk = tid & 15;
    const int rr = tid >> 4;

    for (int k0 = 0; k0 < 1024; k0 += 16) {
#pragma unroll
        for (int p = 0; p < 8; p++) {
            int r = row0 + rr + p * 16;
            int kg = k0 + kk;
            int b = r >> 10, n = r & 1023;
            int h = kg >> 6, d = kg & 63;
            // A[r][kg] = g_o[((b*16+h)*1024+n)*64 + d]
            As[kk][rr + p * 16] = g_o[((b * 16 + h) * 1024 + n) * 64 + d];
        }
#pragma unroll
        for (int p = 0; p < 4; p++) {
            int c = rr + p * 16;
            Bs[kk][c] = w[(col0 + c) * 1024 + k0 + kk];
        }
        __syncthreads();
#pragma unroll
        for (int q = 0; q < 16; q++) {
            float4 a0 = *(const float4*)&As[q][ty * 8];
            float4 a1 = *(const float4*)&As[q][ty * 8 + 4];
            float4 bq = *(const float4*)&Bs[q][tx * 4];
            float a[8] = {a0.x, a0.y, a0.z, a0.w, a1.x, a1.y, a1.z, a1.w};
            float bv[4] = {bq.x, bq.y, bq.z, bq.w};
#pragma unroll
            for (int i = 0; i < 8; i++)
#pragma unroll
                for (int j = 0; j < 4; j++)
                    acc[i][j] = fmaf(a[i], bv[j], acc[i][j]);
        }
        __syncthreads();
    }

#pragma unroll
    for (int i = 0; i < 8; i++) {
        int row = row0 + ty * 8 + i;
#pragma unroll
        for (int j = 0; j < 4; j++) {
            int col = col0 + tx * 4 + j;
            out[row * 1024 + col] = acc[i][j] + bias[col];
        }
    }
}

// ---------------------------------------------------------------------------
// Flash attention: one block per (bh, 128-query tile). KV tile = 64 rows.
// Q and P stored k-major (transposed) in smem so both mainloops are
// outer-product form: 3x LDS.128 per 32 FFMA, conflict-free compute loads.
// Dynamic smem: Qd[64][132] + Pk[64][132] + KV[64][68] = 84992 B.
// ---------------------------------------------------------------------------
__global__ void __launch_bounds__(256) attn_kernel() {
    extern __shared__ float sm[];
    float* Qd = sm;             // [64 d][132]  (Q^T * SCALE)
    float* Pk = sm + 8448;      // [64 k][132]  (P^T)
    float* KV = sm + 16896;     // K phase: [64 d][68] (K^T) ; V phase: [64 k][68]

    const int tid = threadIdx.x;
    const int tx = tid & 15, ty = tid >> 4;
    const int bh = blockIdx.y;          // 0..127
    const int q0 = blockIdx.x * 128;    // query tile start

    const float* __restrict__ qptr = g_q + (size_t)bh * NN * DD;
    const float* __restrict__ kptr = g_k + (size_t)bh * NN * DD;
    const float* __restrict__ vptr = g_v + (size_t)bh * NN * DD;
    float* __restrict__ optr = g_o + (size_t)bh * NN * DD;

    const int d4 = tid & 15;   // float4 index along D
    const int rr = tid >> 4;

    // Load Q tile transposed (x SCALE): Qd[d][r]
#pragma unroll
    for (int p = 0; p < 8; p++) {
        int r = rr + p * 16;
        float4 qv = *(const float4*)&qptr[(q0 + r) * 64 + d4 * 4];
        Qd[(d4 * 4 + 0) * 132 + r] = qv.x * SCALE;
        Qd[(d4 * 4 + 1) * 132 + r] = qv.y * SCALE;
        Qd[(d4 * 4 + 2) * 132 + r] = qv.z * SCALE;
        Qd[(d4 * 4 + 3) * 132 + r] = qv.w * SCALE;
    }

    float m[8], l[8], o[8][4];
#pragma unroll
    for (int i = 0; i < 8; i++) {
        m[i] = -1e30f; l[i] = 0.f;
#pragma unroll
        for (int j = 0; j < 4; j++) o[i][j] = 0.f;
    }

    for (int kv0 = 0; kv0 < NN; kv0 += 64) {
        __syncthreads();  // prior PV reads of KV/Pk done; Q store done (first iter)
        // Load K tile transposed: KV[d][c]
#pragma unroll
        for (int p = 0; p < 4; p++) {
            int c = rr + p * 16;
            float4 kv = *(const float4*)&kptr[(kv0 + c) * 64 + d4 * 4];
            KV[(d4 * 4 + 0) * 68 + c] = kv.x;
            KV[(d4 * 4 + 1) * 68 + c] = kv.y;
            KV[(d4 * 4 + 2) * 68 + c] = kv.z;
            KV[(d4 * 4 + 3) * 68 + c] = kv.w;
        }
        __syncthreads();

        // S = (Q*SCALE) @ K^T  -> s[8][4], rows ty*8+i, cols tx*4+j
        float s[8][4];
#pragma unroll
        for (int i = 0; i < 8; i++)
#pragma unroll
            for (int j = 0; j < 4; j++) s[i][j] = 0.f;

#pragma unroll 16
        for (int d = 0; d < 64; d++) {
            float4 a0 = *(const float4*)&Qd[d * 132 + ty * 8];
            float4 a1 = *(const float4*)&Qd[d * 132 + ty * 8 + 4];
            float4 bq = *(const float4*)&KV[d * 68 + tx * 4];
            float a[8] = {a0.x, a0.y, a0.z, a0.w, a1.x, a1.y, a1.z, a1.w};
            float bv[4] = {bq.x, bq.y, bq.z, bq.w};
#pragma unroll
            for (int i = 0; i < 8; i++)
#pragma unroll
                for (int j = 0; j < 4; j++)
                    s[i][j] = fmaf(a[i], bv[j], s[i][j]);
        }

        // Online softmax update (rows owned by all 16 tx lanes jointly)
#pragma unroll
        for (int i = 0; i < 8; i++) {
            float mx = fmaxf(fmaxf(s[i][0], s[i][1]), fmaxf(s[i][2], s[i][3]));
#pragma unroll
            for (int off = 8; off > 0; off >>= 1)
                mx = fmaxf(mx, __shfl_xor_sync(0xffffffffu, mx, off));
            float mnew = fmaxf(m[i], mx);
            float alpha = __expf(m[i] - mnew);
            m[i] = mnew;
            float rs = 0.f;
#pragma unroll
            for (int j = 0; j < 4; j++) {
                s[i][j] = __expf(s[i][j] - mnew);
                rs += s[i][j];
            }
#pragma unroll
            for (int off = 8; off > 0; off >>= 1)
                rs += __shfl_xor_sync(0xffffffffu, rs, off);
            l[i] = l[i] * alpha + rs;
#pragma unroll
            for (int j = 0; j < 4; j++) o[i][j] *= alpha;
        }

        // Store P transposed: Pk[k][r], k = tx*4+j, r = ty*8+i
#pragma unroll
        for (int j = 0; j < 4; j++)
#pragma unroll
            for (int i = 0; i < 8; i++)
                Pk[(tx * 4 + j) * 132 + ty * 8 + i] = s[i][j];
        __syncthreads();  // Pk ready; K reads of KV done

        // Load V tile (row-major): KV[k][dcol]
#pragma unroll
        for (int p = 0; p < 4; p++) {
            int kr = rr + p * 16;
            *(float4*)&KV[kr * 68 + d4 * 4] =
                *(const float4*)&vptr[(kv0 + kr) * 64 + d4 * 4];
        }
        __syncthreads();

        // O += P @ V
#pragma unroll 16
        for (int k = 0; k < 64; k++) {
            float4 p0 = *(const float4*)&Pk[k * 132 + ty * 8];
            float4 p1 = *(const float4*)&Pk[k * 132 + ty * 8 + 4];
            float4 vv = *(const float4*)&KV[k * 68 + tx * 4];
            float a[8] = {p0.x, p0.y, p0.z, p0.w, p1.x, p1.y, p1.z, p1.w};
            float bv[4] = {vv.x, vv.y, vv.z, vv.w};
#pragma unroll
            for (int i = 0; i < 8; i++)
#pragma unroll
                for (int j = 0; j < 4; j++)
                    o[i][j] = fmaf(a[i], bv[j], o[i][j]);
        }
    }

    // Normalize + write [bh][n][d]
#pragma unroll
    for (int i = 0; i < 8; i++) {
        float inv = 1.f / l[i];
        int r = q0 + ty * 8 + i;
        float4 ov;
        ov.x = o[i][0] * inv; ov.y = o[i][1] * inv;
        ov.z = o[i][2] * inv; ov.w = o[i][3] * inv;
        *(float4*)&optr[r * 64 + tx * 4] = ov;
    }
}

// ---------------------------------------------------------------------------
extern "C" void kernel_launch(void* const* d_in, const int* in_sizes, int n_in,
                              void* d_out, int out_size) {
    const float* x     = (const float*)d_in[0];
    const float* w_in  = (const float*)d_in[1];
    const float* b_in  = (const float*)d_in[2];
    const float* w_out = (const float*)d_in[3];
    const float* b_out = (const float*)d_in[4];
    float* out = (float*)d_out;

    static bool attr_set = false;
    if (!attr_set) {
        cudaFuncSetAttribute(attn_kernel,
                             cudaFuncAttributeMaxDynamicSharedMemorySize, 84992);
        attr_set = true;
    }

    // 1) QKV projection: [8192,1024] x [1024,3072]
    gemm_qkv_kernel<<<dim3(48, 64), 256>>>(x, w_in, b_in);
    // 2) Attention: 128 (b,h) pairs x 8 query tiles of 128
    attn_kernel<<<dim3(8, 128), 256, 84992>>>();
    // 3) Output projection: [8192,1024] x [1024,1024]
    gemm_out_kernel<<<dim3(16, 64), 256>>>(w_out, b_out, out);
}

// round 4
// speedup vs baseline: 1.7215x; 1.7215x over previous
#include <cuda_runtime.h>
#include <cuda_bf16.h>
#include <cstdint>

// Problem constants: B=8, N=1024, C=1024, H=16, D=64
#define BB 8
#define NN 1024
#define CC 1024
#define HH 16
#define DD 64
#define SCALE 0.125f

// ---------------------------------------------------------------------------
// Scratch
// ---------------------------------------------------------------------------
__device__ float g_q[BB*HH*NN*DD];
__device__ float g_k[BB*HH*NN*DD];
__device__ float g_v[BB*HH*NN*DD];

__device__ __nv_bfloat16 g_xhi[BB*NN*CC];
__device__ __nv_bfloat16 g_xlo[BB*NN*CC];
__device__ __nv_bfloat16 g_wihi[3*CC*CC];
__device__ __nv_bfloat16 g_wilo[3*CC*CC];
__device__ __nv_bfloat16 g_wohi[CC*CC];
__device__ __nv_bfloat16 g_wolo[CC*CC];
__device__ __nv_bfloat16 g_ohi[BB*NN*CC];   // attention out, [B*N, C] layout
__device__ __nv_bfloat16 g_olo[BB*NN*CC];

// ---------------------------------------------------------------------------
// Portable (sm_80+) tensor-core helpers: ldmatrix + mma.sync bf16
// ---------------------------------------------------------------------------
__device__ __forceinline__ uint32_t smem_to_u32(const void* p) {
    uint32_t a;
    asm("{ .reg .u64 t; cvta.to.shared.u64 t, %1; cvt.u32.u64 %0, t; }"
        : "=r"(a) : "l"(p));
    return a;
}
__device__ __forceinline__ void ldsm_x4(uint32_t r[4], uint32_t addr) {
    asm volatile("ldmatrix.sync.aligned.m8n8.x4.shared.b16 {%0,%1,%2,%3}, [%4];"
        : "=r"(r[0]), "=r"(r[1]), "=r"(r[2]), "=r"(r[3]) : "r"(addr));
}
__device__ __forceinline__ void mma16816(float c[4], const uint32_t a[4],
                                         const uint32_t b[2]) {
    asm volatile(
        "mma.sync.aligned.m16n8k16.row.col.f32.bf16.bf16.f32 "
        "{%0,%1,%2,%3}, {%4,%5,%6,%7}, {%8,%9}, {%0,%1,%2,%3};"
        : "+f"(c[0]), "+f"(c[1]), "+f"(c[2]), "+f"(c[3])
        : "r"(a[0]), "r"(a[1]), "r"(a[2]), "r"(a[3]), "r"(b[0]), "r"(b[1]));
}
#define CP_ASYNC16(sa, ga) \
    asm volatile("cp.async.cg.shared.global [%0], [%1], 16;" \
                 :: "r"(sa), "l"(ga) : "memory")
#define CP_COMMIT() asm volatile("cp.async.commit_group;" ::: "memory")
#define CP_WAIT1()  asm volatile("cp.async.wait_group 1;" ::: "memory")
#define CP_WAIT0()  asm volatile("cp.async.wait_group 0;" ::: "memory")

// ---------------------------------------------------------------------------
// Split fp32 -> bf16 hi/lo
// ---------------------------------------------------------------------------
__global__ void __launch_bounds__(256) split_kernel(
        const float* __restrict__ src, __nv_bfloat16* __restrict__ hi,
        __nv_bfloat16* __restrict__ lo, int n) {
    int i = blockIdx.x * 256 + threadIdx.x;
    if (i < n) {
        float x = src[i];
        __nv_bfloat16 h = __float2bfloat16(x);
        float r = x - __bfloat162float(h);
        hi[i] = h;
        lo[i] = __float2bfloat16(r);
    }
}

// ---------------------------------------------------------------------------
// mma.sync split-bf16 GEMM: D[M,Ncols] = A[M,1024] @ B[Ncols,1024]^T + bias
// Block tile 128x128, K-chunk 64, cp.async double buffer (2 x 64KB smem).
// 8 warps as 2(m) x 4(n); warp tile 64x32.
// mode 0: scatter qkv to g_q/g_k/g_v ; mode 1: plain fp32 out.
// Smem tile layout: row-major [128 rows][64 bf16], 128B rows, 16B chunk index
// swizzled with (cx ^ (row & 7)) for conflict-free ldmatrix.
// ---------------------------------------------------------------------------
#define STG_STRIDE 65536
#define T_AH 0
#define T_AL 16384
#define T_BH 32768
#define T_BL 49152
#define GEMM_SMEM (2 * STG_STRIDE)

__global__ void __launch_bounds__(256) gemm_mma_kernel(
        const __nv_bfloat16* __restrict__ Ahi, const __nv_bfloat16* __restrict__ Alo,
        const __nv_bfloat16* __restrict__ Bhi, const __nv_bfloat16* __restrict__ Blo,
        const float* __restrict__ bias, float* __restrict__ outp, int mode) {
    extern __shared__ char smem[];
    const uint32_t sbase = smem_to_u32(smem);
    const int tid = threadIdx.x;
    const int wid = tid >> 5, lane = tid & 31;
    const int wm = wid >> 2, wn = wid & 3;
    const int row0 = blockIdx.y * 128, col0 = blockIdx.x * 128;
    const int lr = tid >> 3, lcx = tid & 7;      // loader row / 16B-chunk
    const int mat = lane >> 3, rin = lane & 7;   // ldmatrix addressing

    float cacc[4][4][4];
#pragma unroll
    for (int mi = 0; mi < 4; mi++)
#pragma unroll
        for (int nj = 0; nj < 4; nj++)
#pragma unroll
            for (int e = 0; e < 4; e++) cacc[mi][nj][e] = 0.f;

    auto issue = [&](int stage, int c) {
        const int k0 = c * 64;
        const uint32_t sst = sbase + stage * STG_STRIDE;
#pragma unroll
        for (int p = 0; p < 4; p++) {
            int row = lr + p * 32;
            uint32_t dst = (uint32_t)(row * 128) + ((uint32_t)(lcx ^ (row & 7)) << 4);
            size_t sa = (size_t)(row0 + row) * 1024 + k0 + lcx * 8;
            size_t sb = (size_t)(col0 + row) * 1024 + k0 + lcx * 8;
            CP_ASYNC16(sst + T_AH + dst, Ahi + sa);
            CP_ASYNC16(sst + T_AL + dst, Alo + sa);
            CP_ASYNC16(sst + T_BH + dst, Bhi + sb);
            CP_ASYNC16(sst + T_BL + dst, Blo + sb);
        }
        CP_COMMIT();
    };

    auto compute = [&](int stage) {
        const uint32_t sA  = sbase + stage * STG_STRIDE;
#pragma unroll
        for (int s = 0; s < 4; s++) {
            uint32_t ah[4][4], al[4][4], bh[4][2], bl[4][2];
            const int cx = s * 2 + (mat >> 1);
#pragma unroll
            for (int mi = 0; mi < 4; mi++) {
                int row = wm * 64 + mi * 16 + rin + (mat & 1) * 8;
                uint32_t off = (uint32_t)(row * 128) +
                               ((uint32_t)(cx ^ (row & 7)) << 4);
                ldsm_x4(ah[mi], sA + T_AH + off);
                ldsm_x4(al[mi], sA + T_AL + off);
            }
#pragma unroll
            for (int nf = 0; nf < 2; nf++) {
                int row = wn * 32 + nf * 16 + rin + (mat & 1) * 8;
                uint32_t off = (uint32_t)(row * 128) +
                               ((uint32_t)(cx ^ (row & 7)) << 4);
                uint32_t t[4];
                ldsm_x4(t, sA + T_BH + off);
                bh[nf*2][0] = t[0]; bh[nf*2][1] = t[2];
                bh[nf*2+1][0] = t[1]; bh[nf*2+1][1] = t[3];
                ldsm_x4(t, sA + T_BL + off);
                bl[nf*2][0] = t[0]; bl[nf*2][1] = t[2];
                bl[nf*2+1][0] = t[1]; bl[nf*2+1][1] = t[3];
            }
#pragma unroll
            for (int mi = 0; mi < 4; mi++)
#pragma unroll
                for (int nj = 0; nj < 4; nj++) {
                    mma16816(cacc[mi][nj], ah[mi], bh[nj]);
                    mma16816(cacc[mi][nj], ah[mi], bl[nj]);
                    mma16816(cacc[mi][nj], al[mi], bh[nj]);
                }
        }
    };

    issue(0, 0);
    for (int c = 0; c < 16; c++) {
        if (c < 15) { issue((c + 1) & 1, c + 1); CP_WAIT1(); }
        else        { CP_WAIT0(); }
        __syncthreads();
        compute(c & 1);
        __syncthreads();
    }

    // Epilogue: element (m,n): m = wm*64+mi*16+g(+8), n = wn*32+nj*8+2*c4(+1)
    const int g = lane >> 2, c4 = lane & 3;
#pragma unroll
    for (int mi = 0; mi < 4; mi++)
#pragma unroll
        for (int h = 0; h < 2; h++) {
            int m = wm * 64 + mi * 16 + g + h * 8;
            int row = row0 + m;
            int b = row >> 10, n_ = row & 1023;
#pragma unroll
            for (int nj = 0; nj < 4; nj++) {
                int col = col0 + wn * 32 + nj * 8 + c4 * 2;
                float v0 = cacc[mi][nj][h * 2 + 0] + bias[col];
                float v1 = cacc[mi][nj][h * 2 + 1] + bias[col + 1];
                if (mode == 0) {
#pragma unroll
                    for (int e = 0; e < 2; e++) {
                        int cl = col + e;
                        float v = e ? v1 : v0;
                        int sec = cl >> 10;
                        int ci = cl & 1023;
                        int hh = ci >> 6, d = ci & 63;
                        float* dst = (sec == 0) ? g_q : (sec == 1) ? g_k : g_v;
                        dst[(size_t)(((b * 16 + hh) << 10) | n_) * 64 + d] = v;
                    }
                } else {
                    float2 vv = make_float2(v0, v1);
                    *(float2*)&outp[(size_t)row * 1024 + col] = vv;
                }
            }
        }
}

// ---------------------------------------------------------------------------
// Flash attention (fp32 FMA) — epilogue writes bf16 hi/lo into g_ohi/g_olo
// at [B*N, C] layout for the tensor-core out-projection.
// ---------------------------------------------------------------------------
__global__ void __launch_bounds__(256) attn_kernel() {
    extern __shared__ float sm[];
    float* Qd = sm;             // [64 d][132]
    float* Pk = sm + 8448;      // [64 k][132]
    float* KV = sm + 16896;     // [64][68]

    const int tid = threadIdx.x;
    const int tx = tid & 15, ty = tid >> 4;
    const int bh = blockIdx.y;
    const int q0 = blockIdx.x * 128;

    const float* __restrict__ qptr = g_q + (size_t)bh * NN * DD;
    const float* __restrict__ kptr = g_k + (size_t)bh * NN * DD;
    const float* __restrict__ vptr = g_v + (size_t)bh * NN * DD;

    const int d4 = tid & 15;
    const int rr = tid >> 4;

#pragma unroll
    for (int p = 0; p < 8; p++) {
        int r = rr + p * 16;
        float4 qv = *(const float4*)&qptr[(q0 + r) * 64 + d4 * 4];
        Qd[(d4 * 4 + 0) * 132 + r] = qv.x * SCALE;
        Qd[(d4 * 4 + 1) * 132 + r] = qv.y * SCALE;
        Qd[(d4 * 4 + 2) * 132 + r] = qv.z * SCALE;
        Qd[(d4 * 4 + 3) * 132 + r] = qv.w * SCALE;
    }

    float m[8], l[8], o[8][4];
#pragma unroll
    for (int i = 0; i < 8; i++) {
        m[i] = -1e30f; l[i] = 0.f;
#pragma unroll
        for (int j = 0; j < 4; j++) o[i][j] = 0.f;
    }

    for (int kv0 = 0; kv0 < NN; kv0 += 64) {
        __syncthreads();
#pragma unroll
        for (int p = 0; p < 4; p++) {
            int c = rr + p * 16;
            float4 kv = *(const float4*)&kptr[(kv0 + c) * 64 + d4 * 4];
            KV[(d4 * 4 + 0) * 68 + c] = kv.x;
            KV[(d4 * 4 + 1) * 68 + c] = kv.y;
            KV[(d4 * 4 + 2) * 68 + c] = kv.z;
            KV[(d4 * 4 + 3) * 68 + c] = kv.w;
        }
        __syncthreads();

        float s[8][4];
#pragma unroll
        for (int i = 0; i < 8; i++)
#pragma unroll
            for (int j = 0; j < 4; j++) s[i][j] = 0.f;

#pragma unroll 16
        for (int d = 0; d < 64; d++) {
            float4 a0 = *(const float4*)&Qd[d * 132 + ty * 8];
            float4 a1 = *(const float4*)&Qd[d * 132 + ty * 8 + 4];
            float4 bq = *(const float4*)&KV[d * 68 + tx * 4];
            float a[8] = {a0.x, a0.y, a0.z, a0.w, a1.x, a1.y, a1.z, a1.w};
            float bv[4] = {bq.x, bq.y, bq.z, bq.w};
#pragma unroll
            for (int i = 0; i < 8; i++)
#pragma unroll
                for (int j = 0; j < 4; j++)
                    s[i][j] = fmaf(a[i], bv[j], s[i][j]);
        }

#pragma unroll
        for (int i = 0; i < 8; i++) {
            float mx = fmaxf(fmaxf(s[i][0], s[i][1]), fmaxf(s[i][2], s[i][3]));
#pragma unroll
            for (int off = 8; off > 0; off >>= 1)
                mx = fmaxf(mx, __shfl_xor_sync(0xffffffffu, mx, off));
            float mnew = fmaxf(m[i], mx);
            float alpha = __expf(m[i] - mnew);
            m[i] = mnew;
            float rs = 0.f;
#pragma unroll
            for (int j = 0; j < 4; j++) {
                s[i][j] = __expf(s[i][j] - mnew);
                rs += s[i][j];
            }
#pragma unroll
            for (int off = 8; off > 0; off >>= 1)
                rs += __shfl_xor_sync(0xffffffffu, rs, off);
            l[i] = l[i] * alpha + rs;
#pragma unroll
            for (int j = 0; j < 4; j++) o[i][j] *= alpha;
        }

#pragma unroll
        for (int j = 0; j < 4; j++)
#pragma unroll
            for (int i = 0; i < 8; i++)
                Pk[(tx * 4 + j) * 132 + ty * 8 + i] = s[i][j];
        __syncthreads();

#pragma unroll
        for (int p = 0; p < 4; p++) {
            int kr = rr + p * 16;
            *(float4*)&KV[kr * 68 + d4 * 4] =
                *(const float4*)&vptr[(kv0 + kr) * 64 + d4 * 4];
        }
        __syncthreads();

#pragma unroll 16
        for (int k = 0; k < 64; k++) {
            float4 p0 = *(const float4*)&Pk[k * 132 + ty * 8];
            float4 p1 = *(const float4*)&Pk[k * 132 + ty * 8 + 4];
            float4 vv = *(const float4*)&KV[k * 68 + tx * 4];
            float a[8] = {p0.x, p0.y, p0.z, p0.w, p1.x, p1.y, p1.z, p1.w};
            float bv[4] = {vv.x, vv.y, vv.z, vv.w};
#pragma unroll
            for (int i = 0; i < 8; i++)
#pragma unroll
                for (int j = 0; j < 4; j++)
                    o[i][j] = fmaf(a[i], bv[j], o[i][j]);
        }
    }

    // epilogue: write bf16 hi/lo into [B*N, C] (row = b*1024+n, col = h*64+d)
    const int b = bh >> 4, h = bh & 15;
#pragma unroll
    for (int i = 0; i < 8; i++) {
        float inv = 1.f / l[i];
        int r = q0 + ty * 8 + i;
        size_t base = (size_t)(b * 1024 + r) * 1024 + h * 64 + tx * 4;
#pragma unroll
        for (int j = 0; j < 4; j++) {
            float v = o[i][j] * inv;
            __nv_bfloat16 hbf = __float2bfloat16(v);
            float rres = v - __bfloat162float(hbf);
            g_ohi[base + j] = hbf;
            g_olo[base + j] = __float2bfloat16(rres);
        }
    }
}

// ---------------------------------------------------------------------------
extern "C" void kernel_launch(void* const* d_in, const int* in_sizes, int n_in,
                              void* d_out, int out_size) {
    const float* x     = (const float*)d_in[0];
    const float* w_in  = (const float*)d_in[1];
    const float* b_in  = (const float*)d_in[2];
    const float* w_out = (const float*)d_in[3];
    const float* b_out = (const float*)d_in[4];
    float* out = (float*)d_out;

    static bool attr_set = false;
    if (!attr_set) {
        cudaFuncSetAttribute(attn_kernel,
                             cudaFuncAttributeMaxDynamicSharedMemorySize, 84992);
        cudaFuncSetAttribute(gemm_mma_kernel,
                             cudaFuncAttributeMaxDynamicSharedMemorySize, GEMM_SMEM);
        attr_set = true;
    }

    __nv_bfloat16 *xhi, *xlo, *wihi, *wilo, *wohi, *wolo, *ohi, *olo;
    cudaGetSymbolAddress((void**)&xhi,  g_xhi);
    cudaGetSymbolAddress((void**)&xlo,  g_xlo);
    cudaGetSymbolAddress((void**)&wihi, g_wihi);
    cudaGetSymbolAddress((void**)&wilo, g_wilo);
    cudaGetSymbolAddress((void**)&wohi, g_wohi);
    cudaGetSymbolAddress((void**)&wolo, g_wolo);
    cudaGetSymbolAddress((void**)&ohi,  g_ohi);
    cudaGetSymbolAddress((void**)&olo,  g_olo);

    // 1) split inputs to bf16 hi/lo
    split_kernel<<<(BB*NN*CC + 255) / 256, 256>>>(x, xhi, xlo, BB*NN*CC);
    split_kernel<<<(3*CC*CC + 255) / 256, 256>>>(w_in, wihi, wilo, 3*CC*CC);
    split_kernel<<<(CC*CC + 255) / 256, 256>>>(w_out, wohi, wolo, CC*CC);

    // 2) QKV projection on tensor cores: [8192,1024] @ [3072,1024]^T
    gemm_mma_kernel<<<dim3(24, 64), 256, GEMM_SMEM>>>(
        xhi, xlo, wihi, wilo, b_in, nullptr, 0);

    // 3) attention
    attn_kernel<<<dim3(8, 128), 256, 84992>>>();

    // 4) out projection on tensor cores: [8192,1024] @ [1024,1024]^T
    gemm_mma_kernel<<<dim3(8, 64), 256, GEMM_SMEM>>>(
        ohi, olo, wohi, wolo, b_out, out, 1);
}

// round 5
// speedup vs baseline: 2.5798x; 1.4986x over previous
#include <cuda_runtime.h>
#include <cuda_bf16.h>
#include <cstdint>

// Problem constants: B=8, N=1024, C=1024, H=16, D=64
#define BB 8
#define NN 1024
#define CC 1024
#define HH 16
#define DD 64
#define SCALE 0.125f

// ---------------------------------------------------------------------------
// Scratch (all bf16 hi/lo split pairs)
// ---------------------------------------------------------------------------
__device__ __nv_bfloat16 g_qhi[BB*HH*NN*DD];  // [bh][n][d], q pre-scaled by 1/8
__device__ __nv_bfloat16 g_qlo[BB*HH*NN*DD];
__device__ __nv_bfloat16 g_khi[BB*HH*NN*DD];
__device__ __nv_bfloat16 g_klo[BB*HH*NN*DD];
__device__ __nv_bfloat16 g_vhi[BB*HH*NN*DD];
__device__ __nv_bfloat16 g_vlo[BB*HH*NN*DD];

__device__ __nv_bfloat16 g_xhi[BB*NN*CC];
__device__ __nv_bfloat16 g_xlo[BB*NN*CC];
__device__ __nv_bfloat16 g_wihi[3*CC*CC];
__device__ __nv_bfloat16 g_wilo[3*CC*CC];
__device__ __nv_bfloat16 g_wohi[CC*CC];
__device__ __nv_bfloat16 g_wolo[CC*CC];
__device__ __nv_bfloat16 g_ohi[BB*NN*CC];   // attention out, [B*N, C]
__device__ __nv_bfloat16 g_olo[BB*NN*CC];

// ---------------------------------------------------------------------------
// Portable (sm_80+) tensor-core helpers
// ---------------------------------------------------------------------------
__device__ __forceinline__ uint32_t smem_to_u32(const void* p) {
    uint32_t a;
    asm("{ .reg .u64 t; cvta.to.shared.u64 t, %1; cvt.u32.u64 %0, t; }"
        : "=r"(a) : "l"(p));
    return a;
}
__device__ __forceinline__ void ldsm_x4(uint32_t r[4], uint32_t addr) {
    asm volatile("ldmatrix.sync.aligned.m8n8.x4.shared.b16 {%0,%1,%2,%3}, [%4];"
        : "=r"(r[0]), "=r"(r[1]), "=r"(r[2]), "=r"(r[3]) : "r"(addr));
}
__device__ __forceinline__ void ldsm_x4_t(uint32_t r[4], uint32_t addr) {
    asm volatile("ldmatrix.sync.aligned.m8n8.x4.trans.shared.b16 {%0,%1,%2,%3}, [%4];"
        : "=r"(r[0]), "=r"(r[1]), "=r"(r[2]), "=r"(r[3]) : "r"(addr));
}
__device__ __forceinline__ void mma16816(float c[4], const uint32_t a[4],
                                         const uint32_t b[2]) {
    asm volatile(
        "mma.sync.aligned.m16n8k16.row.col.f32.bf16.bf16.f32 "
        "{%0,%1,%2,%3}, {%4,%5,%6,%7}, {%8,%9}, {%0,%1,%2,%3};"
        : "+f"(c[0]), "+f"(c[1]), "+f"(c[2]), "+f"(c[3])
        : "r"(a[0]), "r"(a[1]), "r"(a[2]), "r"(a[3]), "r"(b[0]), "r"(b[1]));
}
#define CP_ASYNC16(sa, ga) \
    asm volatile("cp.async.cg.shared.global [%0], [%1], 16;" \
                 :: "r"(sa), "l"(ga) : "memory")
#define CP_COMMIT() asm volatile("cp.async.commit_group;" ::: "memory")
#define CP_WAIT1()  asm volatile("cp.async.wait_group 1;" ::: "memory")
#define CP_WAIT0()  asm volatile("cp.async.wait_group 0;" ::: "memory")

// swizzled byte offset inside a [rows][64 bf16] tile (128B rows)
__device__ __forceinline__ uint32_t swz(int row, int cx) {
    return (uint32_t)(row * 128) + ((uint32_t)(cx ^ (row & 7)) << 4);
}

// ---------------------------------------------------------------------------
// Split fp32 -> bf16 hi/lo
// ---------------------------------------------------------------------------
__global__ void __launch_bounds__(256) split_kernel(
        const float* __restrict__ src, __nv_bfloat16* __restrict__ hi,
        __nv_bfloat16* __restrict__ lo, int n) {
    int i = blockIdx.x * 256 + threadIdx.x;
    if (i < n) {
        float x = src[i];
        __nv_bfloat16 h = __float2bfloat16(x);
        float r = x - __bfloat162float(h);
        hi[i] = h;
        lo[i] = __float2bfloat16(r);
    }
}

// ---------------------------------------------------------------------------
// mma.sync split-bf16 GEMM: D[M,Nc] = A[M,1024] @ B[Nc,1024]^T + bias
// Tile 128x128, K-chunk 64, 3-stage cp.async, one sync per chunk.
// mode 0: split+scatter qkv into g_{q,k,v}{hi,lo} (q scaled); mode 1: fp32 out.
// ---------------------------------------------------------------------------
#define STG_STRIDE 65536
#define T_AH 0
#define T_AL 16384
#define T_BH 32768
#define T_BL 49152
#define GEMM_SMEM (3 * STG_STRIDE)

__global__ void __launch_bounds__(256) gemm_mma_kernel(
        const __nv_bfloat16* __restrict__ Ahi, const __nv_bfloat16* __restrict__ Alo,
        const __nv_bfloat16* __restrict__ Bhi, const __nv_bfloat16* __restrict__ Blo,
        const float* __restrict__ bias, float* __restrict__ outp, int mode) {
    extern __shared__ char smem[];
    const uint32_t sbase = smem_to_u32(smem);
    const int tid = threadIdx.x;
    const int wid = tid >> 5, lane = tid & 31;
    const int wm = wid >> 2, wn = wid & 3;
    const int row0 = blockIdx.y * 128, col0 = blockIdx.x * 128;
    const int lr = tid >> 3, lcx = tid & 7;
    const int mat = lane >> 3, rin = lane & 7;

    float cacc[4][4][4];
#pragma unroll
    for (int mi = 0; mi < 4; mi++)
#pragma unroll
        for (int nj = 0; nj < 4; nj++)
#pragma unroll
            for (int e = 0; e < 4; e++) cacc[mi][nj][e] = 0.f;

    auto issue = [&](int stage, int c) {
        const int k0 = c * 64;
        const uint32_t sst = sbase + stage * STG_STRIDE;
#pragma unroll
        for (int p = 0; p < 4; p++) {
            int row = lr + p * 32;
            uint32_t dst = swz(row, lcx);
            size_t sa = (size_t)(row0 + row) * 1024 + k0 + lcx * 8;
            size_t sb = (size_t)(col0 + row) * 1024 + k0 + lcx * 8;
            CP_ASYNC16(sst + T_AH + dst, Ahi + sa);
            CP_ASYNC16(sst + T_AL + dst, Alo + sa);
            CP_ASYNC16(sst + T_BH + dst, Bhi + sb);
            CP_ASYNC16(sst + T_BL + dst, Blo + sb);
        }
        CP_COMMIT();
    };

    auto compute = [&](int stage) {
        const uint32_t sA = sbase + stage * STG_STRIDE;
#pragma unroll
        for (int s = 0; s < 4; s++) {
            uint32_t ah[4][4], al[4][4], bh[4][2], bl[4][2];
            const int cx = s * 2 + (mat >> 1);
#pragma unroll
            for (int mi = 0; mi < 4; mi++) {
                int row = wm * 64 + mi * 16 + rin + (mat & 1) * 8;
                uint32_t off = swz(row, cx);
                ldsm_x4(ah[mi], sA + T_AH + off);
                ldsm_x4(al[mi], sA + T_AL + off);
            }
#pragma unroll
            for (int nf = 0; nf < 2; nf++) {
                int row = wn * 32 + nf * 16 + rin + (mat & 1) * 8;
                uint32_t off = swz(row, cx);
                uint32_t t[4];
                ldsm_x4(t, sA + T_BH + off);
                bh[nf*2][0] = t[0]; bh[nf*2][1] = t[2];
                bh[nf*2+1][0] = t[1]; bh[nf*2+1][1] = t[3];
                ldsm_x4(t, sA + T_BL + off);
                bl[nf*2][0] = t[0]; bl[nf*2][1] = t[2];
                bl[nf*2+1][0] = t[1]; bl[nf*2+1][1] = t[3];
            }
#pragma unroll
            for (int mi = 0; mi < 4; mi++)
#pragma unroll
                for (int nj = 0; nj < 4; nj++) {
                    mma16816(cacc[mi][nj], ah[mi], bh[nj]);
                    mma16816(cacc[mi][nj], ah[mi], bl[nj]);
                    mma16816(cacc[mi][nj], al[mi], bh[nj]);
                }
        }
    };

    issue(0, 0); issue(1, 1);
    for (int c = 0; c < 16; c++) {
        if (c < 15) CP_WAIT1(); else CP_WAIT0();
        __syncthreads();
        if (c + 2 < 16) issue((c + 2) % 3, c + 2);
        compute(c % 3);
    }

    const int g = lane >> 2, c4 = lane & 3;
#pragma unroll
    for (int mi = 0; mi < 4; mi++)
#pragma unroll
        for (int h2 = 0; h2 < 2; h2++) {
            int row = row0 + wm * 64 + mi * 16 + g + h2 * 8;
            int b = row >> 10, n_ = row & 1023;
#pragma unroll
            for (int nj = 0; nj < 4; nj++) {
                int col = col0 + wn * 32 + nj * 8 + c4 * 2;
                float v0 = cacc[mi][nj][h2 * 2 + 0] + bias[col];
                float v1 = cacc[mi][nj][h2 * 2 + 1] + bias[col + 1];
                if (mode == 0) {
                    int sec = col >> 10;
                    int ci = col & 1023;
                    int hh = ci >> 6, d = ci & 63;
                    if (sec == 0) { v0 *= SCALE; v1 *= SCALE; }
                    __nv_bfloat162 hi2 = __floats2bfloat162_rn(v0, v1);
                    float r0 = v0 - __bfloat162float(hi2.x);
                    float r1 = v1 - __bfloat162float(hi2.y);
                    __nv_bfloat162 lo2 = __floats2bfloat162_rn(r0, r1);
                    size_t idx = ((size_t)(((b * 16 + hh) << 10) | n_)) * 64 + d;
                    __nv_bfloat16 *dh = (sec == 0) ? g_qhi : (sec == 1) ? g_khi : g_vhi;
                    __nv_bfloat16 *dl = (sec == 0) ? g_qlo : (sec == 1) ? g_klo : g_vlo;
                    *(uint32_t*)&dh[idx] = *(uint32_t*)&hi2;
                    *(uint32_t*)&dl[idx] = *(uint32_t*)&lo2;
                } else {
                    float2 vv = make_float2(v0, v1);
                    *(float2*)&outp[(size_t)row * 1024 + col] = vv;
                }
            }
        }
}

// ---------------------------------------------------------------------------
// Tensor-core flash attention. One CTA per (bh, 128-query tile); 8 warps,
// each warp owns 16 q rows x full kv. KV tile = 64, double-buffered cp.async.
// S = Qhi.Khi + Qhi.Klo + Qlo.Khi  (q pre-scaled by 1/8)
// O += Phi.Vhi + Phi.Vlo + Plo.Vhi (P split from fp32 accumulators)
// Smem: Qhi 16K | Qlo 16K | 2 stages x (Khi,Klo,Vhi,Vlo 8K each) = 96KB.
// ---------------------------------------------------------------------------
#define AT_SQH 0
#define AT_SQL 16384
#define AT_ST0 32768
#define AT_KH 0
#define AT_KL 8192
#define AT_VH 16384
#define AT_VL 24576
#define ATTN_SMEM 98304

__global__ void __launch_bounds__(256, 2) attn_mma_kernel() {
    extern __shared__ char smem[];
    const uint32_t sbase = smem_to_u32(smem);
    const int tid = threadIdx.x;
    const int wid = tid >> 5, lane = tid & 31;
    const int bh = blockIdx.y, q0 = blockIdx.x * 128;
    const int b = bh >> 4, h = bh & 15;
    const int mat = lane >> 3, rin = lane & 7;
    const int g = lane >> 2, c4 = lane & 3;

    const __nv_bfloat16* __restrict__ qhp = g_qhi + (size_t)bh * NN * DD;
    const __nv_bfloat16* __restrict__ qlp = g_qlo + (size_t)bh * NN * DD;
    const __nv_bfloat16* __restrict__ khp = g_khi + (size_t)bh * NN * DD;
    const __nv_bfloat16* __restrict__ klp = g_klo + (size_t)bh * NN * DD;
    const __nv_bfloat16* __restrict__ vhp = g_vhi + (size_t)bh * NN * DD;
    const __nv_bfloat16* __restrict__ vlp = g_vlo + (size_t)bh * NN * DD;

    // Q tile load (hi+lo): 1024 16B-chunks each
#pragma unroll
    for (int p = 0; p < 4; p++) {
        int chunk = tid + p * 256;
        int row = chunk >> 3, cx = chunk & 7;
        uint32_t dst = swz(row, cx);
        size_t src = (size_t)(q0 + row) * 64 + cx * 8;
        CP_ASYNC16(sbase + AT_SQH + dst, qhp + src);
        CP_ASYNC16(sbase + AT_SQL + dst, qlp + src);
    }
    CP_COMMIT();

    auto issue_kv = [&](int st, int kt) {
        const uint32_t sb = sbase + AT_ST0 + st * 32768;
        const size_t base = (size_t)(kt * 64) * 64;
#pragma unroll
        for (int p = 0; p < 2; p++) {
            int chunk = tid + p * 256;
            int row = chunk >> 3, cx = chunk & 7;
            uint32_t dst = swz(row, cx);
            size_t src = base + (size_t)row * 64 + cx * 8;
            CP_ASYNC16(sb + AT_KH + dst, khp + src);
            CP_ASYNC16(sb + AT_KL + dst, klp + src);
            CP_ASYNC16(sb + AT_VH + dst, vhp + src);
            CP_ASYNC16(sb + AT_VL + dst, vlp + src);
        }
        CP_COMMIT();
    };
    issue_kv(0, 0);
    issue_kv(1, 1);

    float m0 = -1e30f, m1 = -1e30f, l0 = 0.f, l1 = 0.f;
    float oacc[8][4];
#pragma unroll
    for (int i = 0; i < 8; i++)
#pragma unroll
        for (int e = 0; e < 4; e++) oacc[i][e] = 0.f;

    for (int kt = 0; kt < 16; kt++) {
        if (kt < 15) CP_WAIT1(); else CP_WAIT0();
        __syncthreads();
        const uint32_t skv = sbase + AT_ST0 + (kt & 1) * 32768;

        // ---- S = Q @ K^T (3-term split) ----
        float sacc[8][4];
#pragma unroll
        for (int i = 0; i < 8; i++)
#pragma unroll
            for (int e = 0; e < 4; e++) sacc[i][e] = 0.f;

#pragma unroll
        for (int s = 0; s < 4; s++) {
            const int cx = s * 2 + (mat >> 1);
            uint32_t qh[4], ql[4];
            {
                int row = wid * 16 + (mat & 1) * 8 + rin;
                uint32_t off = swz(row, cx);
                ldsm_x4(qh, sbase + AT_SQH + off);
                ldsm_x4(ql, sbase + AT_SQL + off);
            }
#pragma unroll
            for (int t = 0; t < 4; t++) {
                int krow = t * 16 + (mat & 1) * 8 + rin;
                uint32_t off = swz(krow, cx);
                uint32_t th[4], tl[4];
                ldsm_x4(th, skv + AT_KH + off);
                ldsm_x4(tl, skv + AT_KL + off);
                uint32_t bh0[2] = {th[0], th[2]}, bh1[2] = {th[1], th[3]};
                uint32_t bl0[2] = {tl[0], tl[2]}, bl1[2] = {tl[1], tl[3]};
                mma16816(sacc[2*t],   qh, bh0);
                mma16816(sacc[2*t],   qh, bl0);
                mma16816(sacc[2*t],   ql, bh0);
                mma16816(sacc[2*t+1], qh, bh1);
                mma16816(sacc[2*t+1], qh, bl1);
                mma16816(sacc[2*t+1], ql, bh1);
            }
        }

        // ---- online softmax (warp-local) ----
        float mx0 = -1e30f, mx1 = -1e30f;
#pragma unroll
        for (int i = 0; i < 8; i++) {
            mx0 = fmaxf(mx0, fmaxf(sacc[i][0], sacc[i][1]));
            mx1 = fmaxf(mx1, fmaxf(sacc[i][2], sacc[i][3]));
        }
        mx0 = fmaxf(mx0, __shfl_xor_sync(0xffffffffu, mx0, 1));
        mx0 = fmaxf(mx0, __shfl_xor_sync(0xffffffffu, mx0, 2));
        mx1 = fmaxf(mx1, __shfl_xor_sync(0xffffffffu, mx1, 1));
        mx1 = fmaxf(mx1, __shfl_xor_sync(0xffffffffu, mx1, 2));
        float mn0 = fmaxf(m0, mx0), mn1 = fmaxf(m1, mx1);
        float al0 = __expf(m0 - mn0), al1 = __expf(m1 - mn1);
        m0 = mn0; m1 = mn1;
        float rs0 = 0.f, rs1 = 0.f;
#pragma unroll
        for (int i = 0; i < 8; i++) {
            sacc[i][0] = __expf(sacc[i][0] - mn0);
            sacc[i][1] = __expf(sacc[i][1] - mn0);
            sacc[i][2] = __expf(sacc[i][2] - mn1);
            sacc[i][3] = __expf(sacc[i][3] - mn1);
            rs0 += sacc[i][0] + sacc[i][1];
            rs1 += sacc[i][2] + sacc[i][3];
        }
        rs0 += __shfl_xor_sync(0xffffffffu, rs0, 1);
        rs0 += __shfl_xor_sync(0xffffffffu, rs0, 2);
        rs1 += __shfl_xor_sync(0xffffffffu, rs1, 1);
        rs1 += __shfl_xor_sync(0xffffffffu, rs1, 2);
        l0 = l0 * al0 + rs0;
        l1 = l1 * al1 + rs1;
#pragma unroll
        for (int i = 0; i < 8; i++) {
            oacc[i][0] *= al0; oacc[i][1] *= al0;
            oacc[i][2] *= al1; oacc[i][3] *= al1;
        }

        // ---- O += P @ V (3-term split; P from fp32 regs) ----
#pragma unroll
        for (int s = 0; s < 4; s++) {
            uint32_t ph[4], pl[4];
            {
                float e0 = sacc[2*s][0], e1 = sacc[2*s][1];
                float e2 = sacc[2*s][2], e3 = sacc[2*s][3];
                float f0 = sacc[2*s+1][0], f1 = sacc[2*s+1][1];
                float f2 = sacc[2*s+1][2], f3 = sacc[2*s+1][3];
                __nv_bfloat162 t0 = __floats2bfloat162_rn(e0, e1);
                __nv_bfloat162 t1 = __floats2bfloat162_rn(e2, e3);
                __nv_bfloat162 t2 = __floats2bfloat162_rn(f0, f1);
                __nv_bfloat162 t3 = __floats2bfloat162_rn(f2, f3);
                ph[0] = *(uint32_t*)&t0; ph[1] = *(uint32_t*)&t1;
                ph[2] = *(uint32_t*)&t2; ph[3] = *(uint32_t*)&t3;
                __nv_bfloat162 u0 = __floats2bfloat162_rn(
                    e0 - __bfloat162float(t0.x), e1 - __bfloat162float(t0.y));
                __nv_bfloat162 u1 = __floats2bfloat162_rn(
                    e2 - __bfloat162float(t1.x), e3 - __bfloat162float(t1.y));
                __nv_bfloat162 u2 = __floats2bfloat162_rn(
                    f0 - __bfloat162float(t2.x), f1 - __bfloat162float(t2.y));
                __nv_bfloat162 u3 = __floats2bfloat162_rn(
                    f2 - __bfloat162float(t3.x), f3 - __bfloat162float(t3.y));
                pl[0] = *(uint32_t*)&u0; pl[1] = *(uint32_t*)&u1;
                pl[2] = *(uint32_t*)&u2; pl[3] = *(uint32_t*)&u3;
            }
#pragma unroll
            for (int t = 0; t < 4; t++) {
                int vrow = s * 16 + (mat >> 1) * 8 + rin;
                int cxv = t * 2 + (mat & 1);
                uint32_t off = swz(vrow, cxv);
                uint32_t th[4], tl[4];
                ldsm_x4_t(th, skv + AT_VH + off);
                ldsm_x4_t(tl, skv + AT_VL + off);
                uint32_t vh0[2] = {th[0], th[2]}, vh1[2] = {th[1], th[3]};
                uint32_t vl0[2] = {tl[0], tl[2]}, vl1[2] = {tl[1], tl[3]};
                mma16816(oacc[2*t],   ph, vh0);
                mma16816(oacc[2*t],   ph, vl0);
                mma16816(oacc[2*t],   pl, vh0);
                mma16816(oacc[2*t+1], ph, vh1);
                mma16816(oacc[2*t+1], ph, vl1);
                mma16816(oacc[2*t+1], pl, vh1);
            }
        }
        __syncthreads();
        if (kt + 2 < 16) issue_kv(kt & 1, kt + 2);
    }

    // ---- epilogue: normalize, split bf16 hi/lo, write [B*N, C] ----
    float inv0 = 1.f / l0, inv1 = 1.f / l1;
    int r0 = q0 + wid * 16 + g;
    int r1 = r0 + 8;
#pragma unroll
    for (int nj = 0; nj < 8; nj++) {
        int col = h * 64 + nj * 8 + c4 * 2;
        {
            float v0 = oacc[nj][0] * inv0, v1 = oacc[nj][1] * inv0;
            __nv_bfloat162 hi2 = __floats2bfloat162_rn(v0, v1);
            __nv_bfloat162 lo2 = __floats2bfloat162_rn(
                v0 - __bfloat162float(hi2.x), v1 - __bfloat162float(hi2.y));
            size_t idx = (size_t)(b * 1024 + r0) * 1024 + col;
            *(uint32_t*)&g_ohi[idx] = *(uint32_t*)&hi2;
            *(uint32_t*)&g_olo[idx] = *(uint32_t*)&lo2;
        }
        {
            float v0 = oacc[nj][2] * inv1, v1 = oacc[nj][3] * inv1;
            __nv_bfloat162 hi2 = __floats2bfloat162_rn(v0, v1);
            __nv_bfloat162 lo2 = __floats2bfloat162_rn(
                v0 - __bfloat162float(hi2.x), v1 - __bfloat162float(hi2.y));
            size_t idx = (size_t)(b * 1024 + r1) * 1024 + col;
            *(uint32_t*)&g_ohi[idx] = *(uint32_t*)&hi2;
            *(uint32_t*)&g_olo[idx] = *(uint32_t*)&lo2;
        }
    }
}

// ---------------------------------------------------------------------------
extern "C" void kernel_launch(void* const* d_in, const int* in_sizes, int n_in,
                              void* d_out, int out_size) {
    const float* x     = (const float*)d_in[0];
    const float* w_in  = (const float*)d_in[1];
    const float* b_in  = (const float*)d_in[2];
    const float* w_out = (const float*)d_in[3];
    const float* b_out = (const float*)d_in[4];
    float* out = (float*)d_out;

    static bool attr_set = false;
    if (!attr_set) {
        cudaFuncSetAttribute(gemm_mma_kernel,
                             cudaFuncAttributeMaxDynamicSharedMemorySize, GEMM_SMEM);
        cudaFuncSetAttribute(attn_mma_kernel,
                             cudaFuncAttributeMaxDynamicSharedMemorySize, ATTN_SMEM);
        attr_set = true;
    }

    __nv_bfloat16 *xhi, *xlo, *wihi, *wilo, *wohi, *wolo, *ohi, *olo;
    cudaGetSymbolAddress((void**)&xhi,  g_xhi);
    cudaGetSymbolAddress((void**)&xlo,  g_xlo);
    cudaGetSymbolAddress((void**)&wihi, g_wihi);
    cudaGetSymbolAddress((void**)&wilo, g_wilo);
    cudaGetSymbolAddress((void**)&wohi, g_wohi);
    cudaGetSymbolAddress((void**)&wolo, g_wolo);
    cudaGetSymbolAddress((void**)&ohi,  g_ohi);
    cudaGetSymbolAddress((void**)&olo,  g_olo);

    // 1) split inputs to bf16 hi/lo
    split_kernel<<<(BB*NN*CC + 255) / 256, 256>>>(x, xhi, xlo, BB*NN*CC);
    split_kernel<<<(3*CC*CC + 255) / 256, 256>>>(w_in, wihi, wilo, 3*CC*CC);
    split_kernel<<<(CC*CC + 255) / 256, 256>>>(w_out, wohi, wolo, CC*CC);

    // 2) QKV projection (writes split q/k/v, q pre-scaled)
    gemm_mma_kernel<<<dim3(24, 64), 256, GEMM_SMEM>>>(
        xhi, xlo, wihi, wilo, b_in, nullptr, 0);

    // 3) tensor-core flash attention
    attn_mma_kernel<<<dim3(8, 128), 256, ATTN_SMEM>>>();

    // 4) out projection
    gemm_mma_kernel<<<dim3(8, 64), 256, GEMM_SMEM>>>(
        ohi, olo, wohi, wolo, b_out, out, 1);
}

// round 6
// speedup vs baseline: 2.6127x; 1.0127x over previous
#include <cuda_runtime.h>
#include <cuda_bf16.h>
#include <cstdint>

// Problem constants: B=8, N=1024, C=1024, H=16, D=64
#define BB 8
#define NN 1024
#define CC 1024
#define HH 16
#define DD 64
#define SCALE 0.125f

// ---------------------------------------------------------------------------
// Scratch (all bf16 hi/lo split pairs)
// ---------------------------------------------------------------------------
__device__ __nv_bfloat16 g_qhi[BB*HH*NN*DD];  // [bh][n][d], q pre-scaled by 1/8
__device__ __nv_bfloat16 g_qlo[BB*HH*NN*DD];
__device__ __nv_bfloat16 g_khi[BB*HH*NN*DD];
__device__ __nv_bfloat16 g_klo[BB*HH*NN*DD];
__device__ __nv_bfloat16 g_vhi[BB*HH*NN*DD];
__device__ __nv_bfloat16 g_vlo[BB*HH*NN*DD];

__device__ __nv_bfloat16 g_xhi[BB*NN*CC];
__device__ __nv_bfloat16 g_xlo[BB*NN*CC];
__device__ __nv_bfloat16 g_wihi[3*CC*CC];
__device__ __nv_bfloat16 g_wilo[3*CC*CC];
__device__ __nv_bfloat16 g_wohi[CC*CC];
__device__ __nv_bfloat16 g_wolo[CC*CC];
__device__ __nv_bfloat16 g_ohi[BB*NN*CC];   // attention out, [B*N, C]
__device__ __nv_bfloat16 g_olo[BB*NN*CC];

// ---------------------------------------------------------------------------
// Portable (sm_80+) tensor-core helpers
// ---------------------------------------------------------------------------
__device__ __forceinline__ uint32_t smem_to_u32(const void* p) {
    uint32_t a;
    asm("{ .reg .u64 t; cvta.to.shared.u64 t, %1; cvt.u32.u64 %0, t; }"
        : "=r"(a) : "l"(p));
    return a;
}
__device__ __forceinline__ void ldsm_x4(uint32_t r[4], uint32_t addr) {
    asm volatile("ldmatrix.sync.aligned.m8n8.x4.shared.b16 {%0,%1,%2,%3}, [%4];"
        : "=r"(r[0]), "=r"(r[1]), "=r"(r[2]), "=r"(r[3]) : "r"(addr));
}
__device__ __forceinline__ void ldsm_x4_t(uint32_t r[4], uint32_t addr) {
    asm volatile("ldmatrix.sync.aligned.m8n8.x4.trans.shared.b16 {%0,%1,%2,%3}, [%4];"
        : "=r"(r[0]), "=r"(r[1]), "=r"(r[2]), "=r"(r[3]) : "r"(addr));
}
__device__ __forceinline__ void mma16816(float c[4], const uint32_t a[4],
                                         const uint32_t b[2]) {
    asm volatile(
        "mma.sync.aligned.m16n8k16.row.col.f32.bf16.bf16.f32 "
        "{%0,%1,%2,%3}, {%4,%5,%6,%7}, {%8,%9}, {%0,%1,%2,%3};"
        : "+f"(c[0]), "+f"(c[1]), "+f"(c[2]), "+f"(c[3])
        : "r"(a[0]), "r"(a[1]), "r"(a[2]), "r"(a[3]), "r"(b[0]), "r"(b[1]));
}
#define CP_ASYNC16(sa, ga) \
    asm volatile("cp.async.cg.shared.global [%0], [%1], 16;" \
                 :: "r"(sa), "l"(ga) : "memory")
#define CP_COMMIT() asm volatile("cp.async.commit_group;" ::: "memory")
#define CP_WAIT1()  asm volatile("cp.async.wait_group 1;" ::: "memory")
#define CP_WAIT0()  asm volatile("cp.async.wait_group 0;" ::: "memory")

// swizzled byte offset inside a [rows][128B] tile, 16B chunk cx in [0,8)
__device__ __forceinline__ uint32_t swz(int row, int cx) {
    return (uint32_t)(row * 128) + ((uint32_t)(cx ^ (row & 7)) << 4);
}

// ---------------------------------------------------------------------------
// Split fp32 -> bf16 hi/lo
// ---------------------------------------------------------------------------
__global__ void __launch_bounds__(256) split_kernel(
        const float* __restrict__ src, __nv_bfloat16* __restrict__ hi,
        __nv_bfloat16* __restrict__ lo, int n) {
    int i = blockIdx.x * 256 + threadIdx.x;
    if (i < n) {
        float x = src[i];
        __nv_bfloat16 h = __float2bfloat16(x);
        float r = x - __bfloat162float(h);
        hi[i] = h;
        lo[i] = __float2bfloat16(r);
    }
}

// ---------------------------------------------------------------------------
// mma.sync split-bf16 GEMM: D[M,Nc] = A[M,1024] @ B[Nc,1024]^T + bias
// Tile 128x128, K-chunk 32. Smem row = [32 bf16 hi | 32 bf16 lo] (128B),
// 8-chunk XOR swizzle. 3-stage cp.async (3 x 32KB = 96KB) -> 2 CTAs/SM.
// mode 0: split+scatter qkv into g_{q,k,v}{hi,lo} (q scaled); mode 1: fp32 out.
// ---------------------------------------------------------------------------
#define STG_STRIDE 32768
#define T_B 16384
#define GEMM_SMEM (3 * STG_STRIDE)

__global__ void __launch_bounds__(256, 2) gemm_mma_kernel(
        const __nv_bfloat16* __restrict__ Ahi, const __nv_bfloat16* __restrict__ Alo,
        const __nv_bfloat16* __restrict__ Bhi, const __nv_bfloat16* __restrict__ Blo,
        const float* __restrict__ bias, float* __restrict__ outp, int mode) {
    extern __shared__ char smem[];
    const uint32_t sbase = smem_to_u32(smem);
    const int tid = threadIdx.x;
    const int wid = tid >> 5, lane = tid & 31;
    const int wm = wid >> 2, wn = wid & 3;
    const int row0 = blockIdx.y * 128, col0 = blockIdx.x * 128;
    const int mat = lane >> 3, rin = lane & 7;

    float cacc[4][4][4];
#pragma unroll
    for (int mi = 0; mi < 4; mi++)
#pragma unroll
        for (int nj = 0; nj < 4; nj++)
#pragma unroll
            for (int e = 0; e < 4; e++) cacc[mi][nj][e] = 0.f;

    // loader: 2048 16B-chunks per stage (A:1024, B:1024), 8 per thread
    auto issue = [&](int stage, int c) {
        const int k0 = c * 32;
        const uint32_t sst = sbase + stage * STG_STRIDE;
#pragma unroll
        for (int p = 0; p < 4; p++) {
            int id = tid + p * 256;
            int row = id >> 3, cx = id & 7;
            uint32_t dst = swz(row, cx);
            int kg = k0 + (cx & 3) * 8;
            size_t sa = (size_t)(row0 + row) * 1024 + kg;
            size_t sb = (size_t)(col0 + row) * 1024 + kg;
            CP_ASYNC16(sst + dst,       (cx < 4) ? (Ahi + sa) : (Alo + sa));
            CP_ASYNC16(sst + T_B + dst, (cx < 4) ? (Bhi + sb) : (Blo + sb));
        }
        CP_COMMIT();
    };

    auto compute = [&](int stage) {
        const uint32_t sA = sbase + stage * STG_STRIDE;
#pragma unroll
        for (int s = 0; s < 2; s++) {
            uint32_t ah[4][4], al[4][4], bh[4][2], bl[4][2];
            const int cxh = s * 2 + (mat >> 1);
            const int cxl = cxh + 4;
#pragma unroll
            for (int mi = 0; mi < 4; mi++) {
                int row = wm * 64 + mi * 16 + rin + (mat & 1) * 8;
                ldsm_x4(ah[mi], sA + swz(row, cxh));
                ldsm_x4(al[mi], sA + swz(row, cxl));
            }
#pragma unroll
            for (int nf = 0; nf < 2; nf++) {
                int row = wn * 32 + nf * 16 + rin + (mat & 1) * 8;
                uint32_t t[4];
                ldsm_x4(t, sA + T_B + swz(row, cxh));
                bh[nf*2][0] = t[0]; bh[nf*2][1] = t[2];
                bh[nf*2+1][0] = t[1]; bh[nf*2+1][1] = t[3];
                ldsm_x4(t, sA + T_B + swz(row, cxl));
                bl[nf*2][0] = t[0]; bl[nf*2][1] = t[2];
                bl[nf*2+1][0] = t[1]; bl[nf*2+1][1] = t[3];
            }
#pragma unroll
            for (int mi = 0; mi < 4; mi++)
#pragma unroll
                for (int nj = 0; nj < 4; nj++) {
                    mma16816(cacc[mi][nj], ah[mi], bh[nj]);
                    mma16816(cacc[mi][nj], ah[mi], bl[nj]);
                    mma16816(cacc[mi][nj], al[mi], bh[nj]);
                }
        }
    };

    issue(0, 0); issue(1, 1);
    for (int c = 0; c < 32; c++) {
        if (c < 31) CP_WAIT1(); else CP_WAIT0();
        __syncthreads();
        if (c + 2 < 32) issue((c + 2) % 3, c + 2);
        compute(c % 3);
    }

    const int g = lane >> 2, c4 = lane & 3;
#pragma unroll
    for (int mi = 0; mi < 4; mi++)
#pragma unroll
        for (int h2 = 0; h2 < 2; h2++) {
            int row = row0 + wm * 64 + mi * 16 + g + h2 * 8;
            int b = row >> 10, n_ = row & 1023;
#pragma unroll
            for (int nj = 0; nj < 4; nj++) {
                int col = col0 + wn * 32 + nj * 8 + c4 * 2;
                float v0 = cacc[mi][nj][h2 * 2 + 0] + bias[col];
                float v1 = cacc[mi][nj][h2 * 2 + 1] + bias[col + 1];
                if (mode == 0) {
                    int sec = col >> 10;
                    int ci = col & 1023;
                    int hh = ci >> 6, d = ci & 63;
                    if (sec == 0) { v0 *= SCALE; v1 *= SCALE; }
                    __nv_bfloat162 hi2 = __floats2bfloat162_rn(v0, v1);
                    float r0 = v0 - __bfloat162float(hi2.x);
                    float r1 = v1 - __bfloat162float(hi2.y);
                    __nv_bfloat162 lo2 = __floats2bfloat162_rn(r0, r1);
                    size_t idx = ((size_t)(((b * 16 + hh) << 10) | n_)) * 64 + d;
                    __nv_bfloat16 *dh = (sec == 0) ? g_qhi : (sec == 1) ? g_khi : g_vhi;
                    __nv_bfloat16 *dl = (sec == 0) ? g_qlo : (sec == 1) ? g_klo : g_vlo;
                    *(uint32_t*)&dh[idx] = *(uint32_t*)&hi2;
                    *(uint32_t*)&dl[idx] = *(uint32_t*)&lo2;
                } else {
                    float2 vv = make_float2(v0, v1);
                    *(float2*)&outp[(size_t)row * 1024 + col] = vv;
                }
            }
        }
}

// ---------------------------------------------------------------------------
// Tensor-core flash attention. One CTA per (bh, 128-query tile); 8 warps,
// each warp owns 16 q rows x full kv. KV tile = 64, double-buffered cp.async.
// S = Qhi.Khi + Qhi.Klo + Qlo.Khi  (q pre-scaled by 1/8)
// O += Phi.Vhi + Phi.Vlo + Plo.Vhi (P split from fp32 accumulators)
// Smem: Qhi 16K | Qlo 16K | 2 stages x (Khi,Klo,Vhi,Vlo 8K each) = 96KB.
// ---------------------------------------------------------------------------
#define AT_SQH 0
#define AT_SQL 16384
#define AT_ST0 32768
#define AT_KH 0
#define AT_KL 8192
#define AT_VH 16384
#define AT_VL 24576
#define ATTN_SMEM 98304

__global__ void __launch_bounds__(256, 2) attn_mma_kernel() {
    extern __shared__ char smem[];
    const uint32_t sbase = smem_to_u32(smem);
    const int tid = threadIdx.x;
    const int wid = tid >> 5, lane = tid & 31;
    const int bh = blockIdx.y, q0 = blockIdx.x * 128;
    const int b = bh >> 4, h = bh & 15;
    const int mat = lane >> 3, rin = lane & 7;
    const int g = lane >> 2, c4 = lane & 3;

    const __nv_bfloat16* __restrict__ qhp = g_qhi + (size_t)bh * NN * DD;
    const __nv_bfloat16* __restrict__ qlp = g_qlo + (size_t)bh * NN * DD;
    const __nv_bfloat16* __restrict__ khp = g_khi + (size_t)bh * NN * DD;
    const __nv_bfloat16* __restrict__ klp = g_klo + (size_t)bh * NN * DD;
    const __nv_bfloat16* __restrict__ vhp = g_vhi + (size_t)bh * NN * DD;
    const __nv_bfloat16* __restrict__ vlp = g_vlo + (size_t)bh * NN * DD;

    // Q tile load (hi+lo)
#pragma unroll
    for (int p = 0; p < 4; p++) {
        int chunk = tid + p * 256;
        int row = chunk >> 3, cx = chunk & 7;
        uint32_t dst = swz(row, cx);
        size_t src = (size_t)(q0 + row) * 64 + cx * 8;
        CP_ASYNC16(sbase + AT_SQH + dst, qhp + src);
        CP_ASYNC16(sbase + AT_SQL + dst, qlp + src);
    }
    CP_COMMIT();

    auto issue_kv = [&](int st, int kt) {
        const uint32_t sb = sbase + AT_ST0 + st * 32768;
        const size_t base = (size_t)(kt * 64) * 64;
#pragma unroll
        for (int p = 0; p < 2; p++) {
            int chunk = tid + p * 256;
            int row = chunk >> 3, cx = chunk & 7;
            uint32_t dst = swz(row, cx);
            size_t src = base + (size_t)row * 64 + cx * 8;
            CP_ASYNC16(sb + AT_KH + dst, khp + src);
            CP_ASYNC16(sb + AT_KL + dst, klp + src);
            CP_ASYNC16(sb + AT_VH + dst, vhp + src);
            CP_ASYNC16(sb + AT_VL + dst, vlp + src);
        }
        CP_COMMIT();
    };
    issue_kv(0, 0);
    issue_kv(1, 1);

    float m0 = -1e30f, m1 = -1e30f, l0 = 0.f, l1 = 0.f;
    float oacc[8][4];
#pragma unroll
    for (int i = 0; i < 8; i++)
#pragma unroll
        for (int e = 0; e < 4; e++) oacc[i][e] = 0.f;

    for (int kt = 0; kt < 16; kt++) {
        if (kt < 15) CP_WAIT1(); else CP_WAIT0();
        __syncthreads();
        const uint32_t skv = sbase + AT_ST0 + (kt & 1) * 32768;

        // ---- S = Q @ K^T (3-term split) ----
        float sacc[8][4];
#pragma unroll
        for (int i = 0; i < 8; i++)
#pragma unroll
            for (int e = 0; e < 4; e++) sacc[i][e] = 0.f;

#pragma unroll
        for (int s = 0; s < 4; s++) {
            const int cx = s * 2 + (mat >> 1);
            uint32_t qh[4], ql[4];
            {
                int row = wid * 16 + (mat & 1) * 8 + rin;
                uint32_t off = swz(row, cx);
                ldsm_x4(qh, sbase + AT_SQH + off);
                ldsm_x4(ql, sbase + AT_SQL + off);
            }
#pragma unroll
            for (int t = 0; t < 4; t++) {
                int krow = t * 16 + (mat & 1) * 8 + rin;
                uint32_t off = swz(krow, cx);
                uint32_t th[4], tl[4];
                ldsm_x4(th, skv + AT_KH + off);
                ldsm_x4(tl, skv + AT_KL + off);
                uint32_t bh0[2] = {th[0], th[2]}, bh1[2] = {th[1], th[3]};
                uint32_t bl0[2] = {tl[0], tl[2]}, bl1[2] = {tl[1], tl[3]};
                mma16816(sacc[2*t],   qh, bh0);
                mma16816(sacc[2*t],   qh, bl0);
                mma16816(sacc[2*t],   ql, bh0);
                mma16816(sacc[2*t+1], qh, bh1);
                mma16816(sacc[2*t+1], qh, bl1);
                mma16816(sacc[2*t+1], ql, bh1);
            }
        }

        // ---- online softmax (warp-local) ----
        float mx0 = -1e30f, mx1 = -1e30f;
#pragma unroll
        for (int i = 0; i < 8; i++) {
            mx0 = fmaxf(mx0, fmaxf(sacc[i][0], sacc[i][1]));
            mx1 = fmaxf(mx1, fmaxf(sacc[i][2], sacc[i][3]));
        }
        mx0 = fmaxf(mx0, __shfl_xor_sync(0xffffffffu, mx0, 1));
        mx0 = fmaxf(mx0, __shfl_xor_sync(0xffffffffu, mx0, 2));
        mx1 = fmaxf(mx1, __shfl_xor_sync(0xffffffffu, mx1, 1));
        mx1 = fmaxf(mx1, __shfl_xor_sync(0xffffffffu, mx1, 2));
        float mn0 = fmaxf(m0, mx0), mn1 = fmaxf(m1, mx1);
        float al0 = __expf(m0 - mn0), al1 = __expf(m1 - mn1);
        m0 = mn0; m1 = mn1;
        float rs0 = 0.f, rs1 = 0.f;
#pragma unroll
        for (int i = 0; i < 8; i++) {
            sacc[i][0] = __expf(sacc[i][0] - mn0);
            sacc[i][1] = __expf(sacc[i][1] - mn0);
            sacc[i][2] = __expf(sacc[i][2] - mn1);
            sacc[i][3] = __expf(sacc[i][3] - mn1);
            rs0 += sacc[i][0] + sacc[i][1];
            rs1 += sacc[i][2] + sacc[i][3];
        }
        rs0 += __shfl_xor_sync(0xffffffffu, rs0, 1);
        rs0 += __shfl_xor_sync(0xffffffffu, rs0, 2);
        rs1 += __shfl_xor_sync(0xffffffffu, rs1, 1);
        rs1 += __shfl_xor_sync(0xffffffffu, rs1, 2);
        l0 = l0 * al0 + rs0;
        l1 = l1 * al1 + rs1;
#pragma unroll
        for (int i = 0; i < 8; i++) {
            oacc[i][0] *= al0; oacc[i][1] *= al0;
            oacc[i][2] *= al1; oacc[i][3] *= al1;
        }

        // ---- O += P @ V (3-term split; P from fp32 regs) ----
#pragma unroll
        for (int s = 0; s < 4; s++) {
            uint32_t ph[4], pl[4];
            {
                float e0 = sacc[2*s][0], e1 = sacc[2*s][1];
                float e2 = sacc[2*s][2], e3 = sacc[2*s][3];
                float f0 = sacc[2*s+1][0], f1 = sacc[2*s+1][1];
                float f2 = sacc[2*s+1][2], f3 = sacc[2*s+1][3];
                __nv_bfloat162 t0 = __floats2bfloat162_rn(e0, e1);
                __nv_bfloat162 t1 = __floats2bfloat162_rn(e2, e3);
                __nv_bfloat162 t2 = __floats2bfloat162_rn(f0, f1);
                __nv_bfloat162 t3 = __floats2bfloat162_rn(f2, f3);
                ph[0] = *(uint32_t*)&t0; ph[1] = *(uint32_t*)&t1;
                ph[2] = *(uint32_t*)&t2; ph[3] = *(uint32_t*)&t3;
                __nv_bfloat162 u0 = __floats2bfloat162_rn(
                    e0 - __bfloat162float(t0.x), e1 - __bfloat162float(t0.y));
                __nv_bfloat162 u1 = __floats2bfloat162_rn(
                    e2 - __bfloat162float(t1.x), e3 - __bfloat162float(t1.y));
                __nv_bfloat162 u2 = __floats2bfloat162_rn(
                    f0 - __bfloat162float(t2.x), f1 - __bfloat162float(t2.y));
                __nv_bfloat162 u3 = __floats2bfloat162_rn(
                    f2 - __bfloat162float(t3.x), f3 - __bfloat162float(t3.y));
                pl[0] = *(uint32_t*)&u0; pl[1] = *(uint32_t*)&u1;
                pl[2] = *(uint32_t*)&u2; pl[3] = *(uint32_t*)&u3;
            }
#pragma unroll
            for (int t = 0; t < 4; t++) {
                int vrow = s * 16 + (mat >> 1) * 8 + rin;
                int cxv = t * 2 + (mat & 1);
                uint32_t off = swz(vrow, cxv);
                uint32_t th[4], tl[4];
                ldsm_x4_t(th, skv + AT_VH + off);
                ldsm_x4_t(tl, skv + AT_VL + off);
                uint32_t vh0[2] = {th[0], th[2]}, vh1[2] = {th[1], th[3]};
                uint32_t vl0[2] = {tl[0], tl[2]}, vl1[2] = {tl[1], tl[3]};
                mma16816(oacc[2*t],   ph, vh0);
                mma16816(oacc[2*t],   ph, vl0);
                mma16816(oacc[2*t],   pl, vh0);
                mma16816(oacc[2*t+1], ph, vh1);
                mma16816(oacc[2*t+1], ph, vl1);
                mma16816(oacc[2*t+1], pl, vh1);
            }
        }
        __syncthreads();
        if (kt + 2 < 16) issue_kv(kt & 1, kt + 2);
    }

    // ---- epilogue: normalize, split bf16 hi/lo, write [B*N, C] ----
    float inv0 = 1.f / l0, inv1 = 1.f / l1;
    int r0 = q0 + wid * 16 + g;
    int r1 = r0 + 8;
#pragma unroll
    for (int nj = 0; nj < 8; nj++) {
        int col = h * 64 + nj * 8 + c4 * 2;
        {
            float v0 = oacc[nj][0] * inv0, v1 = oacc[nj][1] * inv0;
            __nv_bfloat162 hi2 = __floats2bfloat162_rn(v0, v1);
            __nv_bfloat162 lo2 = __floats2bfloat162_rn(
                v0 - __bfloat162float(hi2.x), v1 - __bfloat162float(hi2.y));
            size_t idx = (size_t)(b * 1024 + r0) * 1024 + col;
            *(uint32_t*)&g_ohi[idx] = *(uint32_t*)&hi2;
            *(uint32_t*)&g_olo[idx] = *(uint32_t*)&lo2;
        }
        {
            float v0 = oacc[nj][2] * inv1, v1 = oacc[nj][3] * inv1;
            __nv_bfloat162 hi2 = __floats2bfloat162_rn(v0, v1);
            __nv_bfloat162 lo2 = __floats2bfloat162_rn(
                v0 - __bfloat162float(hi2.x), v1 - __bfloat162float(hi2.y));
            size_t idx = (size_t)(b * 1024 + r1) * 1024 + col;
            *(uint32_t*)&g_ohi[idx] = *(uint32_t*)&hi2;
            *(uint32_t*)&g_olo[idx] = *(uint32_t*)&lo2;
        }
    }
}

// ---------------------------------------------------------------------------
extern "C" void kernel_launch(void* const* d_in, const int* in_sizes, int n_in,
                              void* d_out, int out_size) {
    const float* x     = (const float*)d_in[0];
    const float* w_in  = (const float*)d_in[1];
    const float* b_in  = (const float*)d_in[2];
    const float* w_out = (const float*)d_in[3];
    const float* b_out = (const float*)d_in[4];
    float* out = (float*)d_out;

    static bool attr_set = false;
    if (!attr_set) {
        cudaFuncSetAttribute(gemm_mma_kernel,
                             cudaFuncAttributeMaxDynamicSharedMemorySize, GEMM_SMEM);
        cudaFuncSetAttribute(attn_mma_kernel,
                             cudaFuncAttributeMaxDynamicSharedMemorySize, ATTN_SMEM);
        attr_set = true;
    }

    __nv_bfloat16 *xhi, *xlo, *wihi, *wilo, *wohi, *wolo, *ohi, *olo;
    cudaGetSymbolAddress((void**)&xhi,  g_xhi);
    cudaGetSymbolAddress((void**)&xlo,  g_xlo);
    cudaGetSymbolAddress((void**)&wihi, g_wihi);
    cudaGetSymbolAddress((void**)&wilo, g_wilo);
    cudaGetSymbolAddress((void**)&wohi, g_wohi);
    cudaGetSymbolAddress((void**)&wolo, g_wolo);
    cudaGetSymbolAddress((void**)&ohi,  g_ohi);
    cudaGetSymbolAddress((void**)&olo,  g_olo);

    // 1) split inputs to bf16 hi/lo
    split_kernel<<<(BB*NN*CC + 255) / 256, 256>>>(x, xhi, xlo, BB*NN*CC);
    split_kernel<<<(3*CC*CC + 255) / 256, 256>>>(w_in, wihi, wilo, 3*CC*CC);
    split_kernel<<<(CC*CC + 255) / 256, 256>>>(w_out, wohi, wolo, CC*CC);

    // 2) QKV projection (writes split q/k/v, q pre-scaled)
    gemm_mma_kernel<<<dim3(24, 64), 256, GEMM_SMEM>>>(
        xhi, xlo, wihi, wilo, b_in, nullptr, 0);

    // 3) tensor-core flash attention
    attn_mma_kernel<<<dim3(8, 128), 256, ATTN_SMEM>>>();

    // 4) out projection
    gemm_mma_kernel<<<dim3(8, 64), 256, GEMM_SMEM>>>(
        ohi, olo, wohi, wolo, b_out, out, 1);
}

// round 7
// speedup vs baseline: 2.6633x; 1.0194x over previous
#include <cuda_runtime.h>
#include <cuda_bf16.h>
#include <cstdint>

// Problem constants: B=8, N=1024, C=1024, H=16, D=64
#define BB 8
#define NN 1024
#define CC 1024
#define HH 16
#define DD 64
#define SCALE 0.125f

// ---------------------------------------------------------------------------
// Scratch (all bf16 hi/lo split pairs)
// ---------------------------------------------------------------------------
__device__ __nv_bfloat16 g_qhi[BB*HH*NN*DD];  // [bh][n][d], q pre-scaled by 1/8
__device__ __nv_bfloat16 g_qlo[BB*HH*NN*DD];
__device__ __nv_bfloat16 g_khi[BB*HH*NN*DD];
__device__ __nv_bfloat16 g_klo[BB*HH*NN*DD];
__device__ __nv_bfloat16 g_vhi[BB*HH*NN*DD];
__device__ __nv_bfloat16 g_vlo[BB*HH*NN*DD];

__device__ __nv_bfloat16 g_xhi[BB*NN*CC];
__device__ __nv_bfloat16 g_xlo[BB*NN*CC];
__device__ __nv_bfloat16 g_wihi[3*CC*CC];
__device__ __nv_bfloat16 g_wilo[3*CC*CC];
__device__ __nv_bfloat16 g_wohi[CC*CC];
__device__ __nv_bfloat16 g_wolo[CC*CC];
__device__ __nv_bfloat16 g_ohi[BB*NN*CC];   // attention out, [B*N, C]
__device__ __nv_bfloat16 g_olo[BB*NN*CC];

// ---------------------------------------------------------------------------
// Portable (sm_80+) tensor-core helpers
// ---------------------------------------------------------------------------
__device__ __forceinline__ uint32_t smem_to_u32(const void* p) {
    uint32_t a;
    asm("{ .reg .u64 t; cvta.to.shared.u64 t, %1; cvt.u32.u64 %0, t; }"
        : "=r"(a) : "l"(p));
    return a;
}
__device__ __forceinline__ void ldsm_x4(uint32_t r[4], uint32_t addr) {
    asm volatile("ldmatrix.sync.aligned.m8n8.x4.shared.b16 {%0,%1,%2,%3}, [%4];"
        : "=r"(r[0]), "=r"(r[1]), "=r"(r[2]), "=r"(r[3]) : "r"(addr));
}
__device__ __forceinline__ void ldsm_x4_t(uint32_t r[4], uint32_t addr) {
    asm volatile("ldmatrix.sync.aligned.m8n8.x4.trans.shared.b16 {%0,%1,%2,%3}, [%4];"
        : "=r"(r[0]), "=r"(r[1]), "=r"(r[2]), "=r"(r[3]) : "r"(addr));
}
__device__ __forceinline__ void mma16816(float c[4], const uint32_t a[4],
                                         const uint32_t b[2]) {
    asm volatile(
        "mma.sync.aligned.m16n8k16.row.col.f32.bf16.bf16.f32 "
        "{%0,%1,%2,%3}, {%4,%5,%6,%7}, {%8,%9}, {%0,%1,%2,%3};"
        : "+f"(c[0]), "+f"(c[1]), "+f"(c[2]), "+f"(c[3])
        : "r"(a[0]), "r"(a[1]), "r"(a[2]), "r"(a[3]), "r"(b[0]), "r"(b[1]));
}
#define CP_ASYNC16(sa, ga) \
    asm volatile("cp.async.cg.shared.global [%0], [%1], 16;" \
                 :: "r"(sa), "l"(ga) : "memory")
#define CP_COMMIT() asm volatile("cp.async.commit_group;" ::: "memory")
#define CP_WAIT1()  asm volatile("cp.async.wait_group 1;" ::: "memory")
#define CP_WAIT0()  asm volatile("cp.async.wait_group 0;" ::: "memory")

// swizzled byte offset inside a [rows][128B] tile, 16B chunk cx in [0,8)
__device__ __forceinline__ uint32_t swz(int row, int cx) {
    return (uint32_t)(row * 128) + ((uint32_t)(cx ^ (row & 7)) << 4);
}

// ---------------------------------------------------------------------------
// Split fp32 -> bf16 hi/lo
// ---------------------------------------------------------------------------
__global__ void __launch_bounds__(256) split_kernel(
        const float* __restrict__ src, __nv_bfloat16* __restrict__ hi,
        __nv_bfloat16* __restrict__ lo, int n) {
    int i = blockIdx.x * 256 + threadIdx.x;
    if (i < n) {
        float x = src[i];
        __nv_bfloat16 h = __float2bfloat16(x);
        float r = x - __bfloat162float(h);
        hi[i] = h;
        lo[i] = __float2bfloat16(r);
    }
}

// ---------------------------------------------------------------------------
// mma.sync split-bf16 GEMM: D[M,Nc] = A[M,1024] @ B[Nc,1024]^T + bias
// Tile 128x128, K-chunk 32. Smem row = [32 bf16 hi | 32 bf16 lo] (128B).
// 3-stage cp.async (96KB) -> 2 CTAs/SM. Chunk loop manually unrolled by 3
// (compile-time stage bases); term-major MMA order for dependency spacing.
// ---------------------------------------------------------------------------
#define STG_STRIDE 32768
#define T_B 16384
#define GEMM_SMEM (3 * STG_STRIDE)

__global__ void __launch_bounds__(256, 2) gemm_mma_kernel(
        const __nv_bfloat16* __restrict__ Ahi, const __nv_bfloat16* __restrict__ Alo,
        const __nv_bfloat16* __restrict__ Bhi, const __nv_bfloat16* __restrict__ Blo,
        const float* __restrict__ bias, float* __restrict__ outp, int mode) {
    extern __shared__ char smem[];
    const uint32_t sbase = smem_to_u32(smem);
    const int tid = threadIdx.x;
    const int wid = tid >> 5, lane = tid & 31;
    const int wm = wid >> 2, wn = wid & 3;
    const int row0 = blockIdx.y * 128, col0 = blockIdx.x * 128;
    const int mat = lane >> 3, rin = lane & 7;

    float cacc[4][4][4];
#pragma unroll
    for (int mi = 0; mi < 4; mi++)
#pragma unroll
        for (int nj = 0; nj < 4; nj++)
#pragma unroll
            for (int e = 0; e < 4; e++) cacc[mi][nj][e] = 0.f;

    // loader: 2048 16B-chunks per stage (A:1024, B:1024), 8 per thread
    auto issue = [&](int stage, int c) {
        const int k0 = c * 32;
        const uint32_t sst = sbase + stage * STG_STRIDE;
#pragma unroll
        for (int p = 0; p < 4; p++) {
            int id = tid + p * 256;
            int row = id >> 3, cx = id & 7;
            uint32_t dst = swz(row, cx);
            int kg = k0 + (cx & 3) * 8;
            size_t sa = (size_t)(row0 + row) * 1024 + kg;
            size_t sb = (size_t)(col0 + row) * 1024 + kg;
            CP_ASYNC16(sst + dst,       (cx < 4) ? (Ahi + sa) : (Alo + sa));
            CP_ASYNC16(sst + T_B + dst, (cx < 4) ? (Bhi + sb) : (Blo + sb));
        }
        CP_COMMIT();
    };

    auto compute = [&](int stage) {
        const uint32_t sA = sbase + stage * STG_STRIDE;
#pragma unroll
        for (int s = 0; s < 2; s++) {
            uint32_t ah[4][4], al[4][4], bh[4][2], bl[4][2];
            const int cxh = s * 2 + (mat >> 1);
            const int cxl = cxh + 4;
#pragma unroll
            for (int mi = 0; mi < 4; mi++) {
                int row = wm * 64 + mi * 16 + rin + (mat & 1) * 8;
                ldsm_x4(ah[mi], sA + swz(row, cxh));
                ldsm_x4(al[mi], sA + swz(row, cxl));
            }
#pragma unroll
            for (int nf = 0; nf < 2; nf++) {
                int row = wn * 32 + nf * 16 + rin + (mat & 1) * 8;
                uint32_t t[4];
                ldsm_x4(t, sA + T_B + swz(row, cxh));
                bh[nf*2][0] = t[0]; bh[nf*2][1] = t[2];
                bh[nf*2+1][0] = t[1]; bh[nf*2+1][1] = t[3];
                ldsm_x4(t, sA + T_B + swz(row, cxl));
                bl[nf*2][0] = t[0]; bl[nf*2][1] = t[2];
                bl[nf*2+1][0] = t[1]; bl[nf*2+1][1] = t[3];
            }
            // term-major: 16 independent MMAs between accumulator reuses
#pragma unroll
            for (int mi = 0; mi < 4; mi++)
#pragma unroll
                for (int nj = 0; nj < 4; nj++)
                    mma16816(cacc[mi][nj], ah[mi], bh[nj]);
#pragma unroll
            for (int mi = 0; mi < 4; mi++)
#pragma unroll
                for (int nj = 0; nj < 4; nj++)
                    mma16816(cacc[mi][nj], ah[mi], bl[nj]);
#pragma unroll
            for (int mi = 0; mi < 4; mi++)
#pragma unroll
                for (int nj = 0; nj < 4; nj++)
                    mma16816(cacc[mi][nj], al[mi], bh[nj]);
        }
    };

    auto step = [&](int c, int stage, int nxt) {
        if (c < 31) CP_WAIT1(); else CP_WAIT0();
        __syncthreads();
        if (c + 2 < 32) issue(nxt, c + 2);
        compute(stage);
    };

    issue(0, 0); issue(1, 1);
    // 32 chunks, manually unrolled x3 so stage indices are compile-time
#pragma unroll 1
    for (int cb = 0; cb < 30; cb += 3) {
        step(cb + 0, 0, 2);
        step(cb + 1, 1, 0);
        step(cb + 2, 2, 1);
    }
    step(30, 0, 2);
    step(31, 1, 0);

    const int g = lane >> 2, c4 = lane & 3;
#pragma unroll
    for (int mi = 0; mi < 4; mi++)
#pragma unroll
        for (int h2 = 0; h2 < 2; h2++) {
            int row = row0 + wm * 64 + mi * 16 + g + h2 * 8;
            int b = row >> 10, n_ = row & 1023;
#pragma unroll
            for (int nj = 0; nj < 4; nj++) {
                int col = col0 + wn * 32 + nj * 8 + c4 * 2;
                float v0 = cacc[mi][nj][h2 * 2 + 0] + bias[col];
                float v1 = cacc[mi][nj][h2 * 2 + 1] + bias[col + 1];
                if (mode == 0) {
                    int sec = col >> 10;
                    int ci = col & 1023;
                    int hh = ci >> 6, d = ci & 63;
                    if (sec == 0) { v0 *= SCALE; v1 *= SCALE; }
                    __nv_bfloat162 hi2 = __floats2bfloat162_rn(v0, v1);
                    float r0 = v0 - __bfloat162float(hi2.x);
                    float r1 = v1 - __bfloat162float(hi2.y);
                    __nv_bfloat162 lo2 = __floats2bfloat162_rn(r0, r1);
                    size_t idx = ((size_t)(((b * 16 + hh) << 10) | n_)) * 64 + d;
                    __nv_bfloat16 *dh = (sec == 0) ? g_qhi : (sec == 1) ? g_khi : g_vhi;
                    __nv_bfloat16 *dl = (sec == 0) ? g_qlo : (sec == 1) ? g_klo : g_vlo;
                    *(uint32_t*)&dh[idx] = *(uint32_t*)&hi2;
                    *(uint32_t*)&dl[idx] = *(uint32_t*)&lo2;
                } else {
                    float2 vv = make_float2(v0, v1);
                    *(float2*)&outp[(size_t)row * 1024 + col] = vv;
                }
            }
        }
}

// ---------------------------------------------------------------------------
// Tensor-core flash attention. One CTA per (bh, 128-query tile); 8 warps,
// each warp owns 16 q rows x full kv. KV tile = 64, double-buffered cp.async.
// kt loop manually unrolled x2 (compile-time KV stage bases).
// ---------------------------------------------------------------------------
#define AT_SQH 0
#define AT_SQL 16384
#define AT_ST0 32768
#define AT_KH 0
#define AT_KL 8192
#define AT_VH 16384
#define AT_VL 24576
#define ATTN_SMEM 98304

__global__ void __launch_bounds__(256, 2) attn_mma_kernel() {
    extern __shared__ char smem[];
    const uint32_t sbase = smem_to_u32(smem);
    const int tid = threadIdx.x;
    const int wid = tid >> 5, lane = tid & 31;
    const int bh = blockIdx.y, q0 = blockIdx.x * 128;
    const int b = bh >> 4, h = bh & 15;
    const int mat = lane >> 3, rin = lane & 7;
    const int g = lane >> 2, c4 = lane & 3;

    const __nv_bfloat16* __restrict__ qhp = g_qhi + (size_t)bh * NN * DD;
    const __nv_bfloat16* __restrict__ qlp = g_qlo + (size_t)bh * NN * DD;
    const __nv_bfloat16* __restrict__ khp = g_khi + (size_t)bh * NN * DD;
    const __nv_bfloat16* __restrict__ klp = g_klo + (size_t)bh * NN * DD;
    const __nv_bfloat16* __restrict__ vhp = g_vhi + (size_t)bh * NN * DD;
    const __nv_bfloat16* __restrict__ vlp = g_vlo + (size_t)bh * NN * DD;

    // Q tile load (hi+lo)
#pragma unroll
    for (int p = 0; p < 4; p++) {
        int chunk = tid + p * 256;
        int row = chunk >> 3, cx = chunk & 7;
        uint32_t dst = swz(row, cx);
        size_t src = (size_t)(q0 + row) * 64 + cx * 8;
        CP_ASYNC16(sbase + AT_SQH + dst, qhp + src);
        CP_ASYNC16(sbase + AT_SQL + dst, qlp + src);
    }
    CP_COMMIT();

    auto issue_kv = [&](int st, int kt) {
        const uint32_t sb = sbase + AT_ST0 + st * 32768;
        const size_t base = (size_t)(kt * 64) * 64;
#pragma unroll
        for (int p = 0; p < 2; p++) {
            int chunk = tid + p * 256;
            int row = chunk >> 3, cx = chunk & 7;
            uint32_t dst = swz(row, cx);
            size_t src = base + (size_t)row * 64 + cx * 8;
            CP_ASYNC16(sb + AT_KH + dst, khp + src);
            CP_ASYNC16(sb + AT_KL + dst, klp + src);
            CP_ASYNC16(sb + AT_VH + dst, vhp + src);
            CP_ASYNC16(sb + AT_VL + dst, vlp + src);
        }
        CP_COMMIT();
    };
    issue_kv(0, 0);
    issue_kv(1, 1);

    float m0 = -1e30f, m1 = -1e30f, l0 = 0.f, l1 = 0.f;
    float oacc[8][4];
#pragma unroll
    for (int i = 0; i < 8; i++)
#pragma unroll
        for (int e = 0; e < 4; e++) oacc[i][e] = 0.f;

    auto astep = [&](int kt, int st) {
        if (kt < 15) CP_WAIT1(); else CP_WAIT0();
        __syncthreads();
        const uint32_t skv = sbase + AT_ST0 + st * 32768;

        // ---- S = Q @ K^T (3-term split) ----
        float sacc[8][4];
#pragma unroll
        for (int i = 0; i < 8; i++)
#pragma unroll
            for (int e = 0; e < 4; e++) sacc[i][e] = 0.f;

#pragma unroll
        for (int s = 0; s < 4; s++) {
            const int cx = s * 2 + (mat >> 1);
            uint32_t qh[4], ql[4];
            {
                int row = wid * 16 + (mat & 1) * 8 + rin;
                uint32_t off = swz(row, cx);
                ldsm_x4(qh, sbase + AT_SQH + off);
                ldsm_x4(ql, sbase + AT_SQL + off);
            }
#pragma unroll
            for (int t = 0; t < 4; t++) {
                int krow = t * 16 + (mat & 1) * 8 + rin;
                uint32_t off = swz(krow, cx);
                uint32_t th[4], tl[4];
                ldsm_x4(th, skv + AT_KH + off);
                ldsm_x4(tl, skv + AT_KL + off);
                uint32_t bh0[2] = {th[0], th[2]}, bh1[2] = {th[1], th[3]};
                uint32_t bl0[2] = {tl[0], tl[2]}, bl1[2] = {tl[1], tl[3]};
                // pair-interleaved terms (2 independent between reuses)
                mma16816(sacc[2*t],   qh, bh0);
                mma16816(sacc[2*t+1], qh, bh1);
                mma16816(sacc[2*t],   qh, bl0);
                mma16816(sacc[2*t+1], qh, bl1);
                mma16816(sacc[2*t],   ql, bh0);
                mma16816(sacc[2*t+1], ql, bh1);
            }
        }

        // ---- online softmax (warp-local) ----
        float mx0 = -1e30f, mx1 = -1e30f;
#pragma unroll
        for (int i = 0; i < 8; i++) {
            mx0 = fmaxf(mx0, fmaxf(sacc[i][0], sacc[i][1]));
            mx1 = fmaxf(mx1, fmaxf(sacc[i][2], sacc[i][3]));
        }
        mx0 = fmaxf(mx0, __shfl_xor_sync(0xffffffffu, mx0, 1));
        mx0 = fmaxf(mx0, __shfl_xor_sync(0xffffffffu, mx0, 2));
        mx1 = fmaxf(mx1, __shfl_xor_sync(0xffffffffu, mx1, 1));
        mx1 = fmaxf(mx1, __shfl_xor_sync(0xffffffffu, mx1, 2));
        float mn0 = fmaxf(m0, mx0), mn1 = fmaxf(m1, mx1);
        float al0 = __expf(m0 - mn0), al1 = __expf(m1 - mn1);
        m0 = mn0; m1 = mn1;
        float rs0 = 0.f, rs1 = 0.f;
#pragma unroll
        for (int i = 0; i < 8; i++) {
            sacc[i][0] = __expf(sacc[i][0] - mn0);
            sacc[i][1] = __expf(sacc[i][1] - mn0);
            sacc[i][2] = __expf(sacc[i][2] - mn1);
            sacc[i][3] = __expf(sacc[i][3] - mn1);
            rs0 += sacc[i][0] + sacc[i][1];
            rs1 += sacc[i][2] + sacc[i][3];
        }
        rs0 += __shfl_xor_sync(0xffffffffu, rs0, 1);
        rs0 += __shfl_xor_sync(0xffffffffu, rs0, 2);
        rs1 += __shfl_xor_sync(0xffffffffu, rs1, 1);
        rs1 += __shfl_xor_sync(0xffffffffu, rs1, 2);
        l0 = l0 * al0 + rs0;
        l1 = l1 * al1 + rs1;
#pragma unroll
        for (int i = 0; i < 8; i++) {
            oacc[i][0] *= al0; oacc[i][1] *= al0;
            oacc[i][2] *= al1; oacc[i][3] *= al1;
        }

        // ---- O += P @ V (3-term split; P from fp32 regs) ----
#pragma unroll
        for (int s = 0; s < 4; s++) {
            uint32_t ph[4], pl[4];
            {
                float e0 = sacc[2*s][0], e1 = sacc[2*s][1];
                float e2 = sacc[2*s][2], e3 = sacc[2*s][3];
                float f0 = sacc[2*s+1][0], f1 = sacc[2*s+1][1];
                float f2 = sacc[2*s+1][2], f3 = sacc[2*s+1][3];
                __nv_bfloat162 t0 = __floats2bfloat162_rn(e0, e1);
                __nv_bfloat162 t1 = __floats2bfloat162_rn(e2, e3);
                __nv_bfloat162 t2 = __floats2bfloat162_rn(f0, f1);
                __nv_bfloat162 t3 = __floats2bfloat162_rn(f2, f3);
                ph[0] = *(uint32_t*)&t0; ph[1] = *(uint32_t*)&t1;
                ph[2] = *(uint32_t*)&t2; ph[3] = *(uint32_t*)&t3;
                __nv_bfloat162 u0 = __floats2bfloat162_rn(
                    e0 - __bfloat162float(t0.x), e1 - __bfloat162float(t0.y));
                __nv_bfloat162 u1 = __floats2bfloat162_rn(
                    e2 - __bfloat162float(t1.x), e3 - __bfloat162float(t1.y));
                __nv_bfloat162 u2 = __floats2bfloat162_rn(
                    f0 - __bfloat162float(t2.x), f1 - __bfloat162float(t2.y));
                __nv_bfloat162 u3 = __floats2bfloat162_rn(
                    f2 - __bfloat162float(t3.x), f3 - __bfloat162float(t3.y));
                pl[0] = *(uint32_t*)&u0; pl[1] = *(uint32_t*)&u1;
                pl[2] = *(uint32_t*)&u2; pl[3] = *(uint32_t*)&u3;
            }
#pragma unroll
            for (int t = 0; t < 4; t++) {
                int vrow = s * 16 + (mat >> 1) * 8 + rin;
                int cxv = t * 2 + (mat & 1);
                uint32_t off = swz(vrow, cxv);
                uint32_t th[4], tl[4];
                ldsm_x4_t(th, skv + AT_VH + off);
                ldsm_x4_t(tl, skv + AT_VL + off);
                uint32_t vh0[2] = {th[0], th[2]}, vh1[2] = {th[1], th[3]};
                uint32_t vl0[2] = {tl[0], tl[2]}, vl1[2] = {tl[1], tl[3]};
                mma16816(oacc[2*t],   ph, vh0);
                mma16816(oacc[2*t+1], ph, vh1);
                mma16816(oacc[2*t],   ph, vl0);
                mma16816(oacc[2*t+1], ph, vl1);
                mma16816(oacc[2*t],   pl, vh0);
                mma16816(oacc[2*t+1], pl, vh1);
            }
        }
        __syncthreads();
        if (kt + 2 < 16) issue_kv(st, kt + 2);
    };

#pragma unroll 1
    for (int kt = 0; kt < 16; kt += 2) {
        astep(kt, 0);
        astep(kt + 1, 1);
    }

    // ---- epilogue: normalize, split bf16 hi/lo, write [B*N, C] ----
    float inv0 = 1.f / l0, inv1 = 1.f / l1;
    int r0 = q0 + wid * 16 + g;
    int r1 = r0 + 8;
#pragma unroll
    for (int nj = 0; nj < 8; nj++) {
        int col = h * 64 + nj * 8 + c4 * 2;
        {
            float v0 = oacc[nj][0] * inv0, v1 = oacc[nj][1] * inv0;
            __nv_bfloat162 hi2 = __floats2bfloat162_rn(v0, v1);
            __nv_bfloat162 lo2 = __floats2bfloat162_rn(
                v0 - __bfloat162float(hi2.x), v1 - __bfloat162float(hi2.y));
            size_t idx = (size_t)(b * 1024 + r0) * 1024 + col;
            *(uint32_t*)&g_ohi[idx] = *(uint32_t*)&hi2;
            *(uint32_t*)&g_olo[idx] = *(uint32_t*)&lo2;
        }
        {
            float v0 = oacc[nj][2] * inv1, v1 = oacc[nj][3] * inv1;
            __nv_bfloat162 hi2 = __floats2bfloat162_rn(v0, v1);
            __nv_bfloat162 lo2 = __floats2bfloat162_rn(
                v0 - __bfloat162float(hi2.x), v1 - __bfloat162float(hi2.y));
            size_t idx = (size_t)(b * 1024 + r1) * 1024 + col;
            *(uint32_t*)&g_ohi[idx] = *(uint32_t*)&hi2;
            *(uint32_t*)&g_olo[idx] = *(uint32_t*)&lo2;
        }
    }
}

// ---------------------------------------------------------------------------
extern "C" void kernel_launch(void* const* d_in, const int* in_sizes, int n_in,
                              void* d_out, int out_size) {
    const float* x     = (const float*)d_in[0];
    const float* w_in  = (const float*)d_in[1];
    const float* b_in  = (const float*)d_in[2];
    const float* w_out = (const float*)d_in[3];
    const float* b_out = (const float*)d_in[4];
    float* out = (float*)d_out;

    static bool attr_set = false;
    if (!attr_set) {
        cudaFuncSetAttribute(gemm_mma_kernel,
                             cudaFuncAttributeMaxDynamicSharedMemorySize, GEMM_SMEM);
        cudaFuncSetAttribute(attn_mma_kernel,
                             cudaFuncAttributeMaxDynamicSharedMemorySize, ATTN_SMEM);
        attr_set = true;
    }

    __nv_bfloat16 *xhi, *xlo, *wihi, *wilo, *wohi, *wolo, *ohi, *olo;
    cudaGetSymbolAddress((void**)&xhi,  g_xhi);
    cudaGetSymbolAddress((void**)&xlo,  g_xlo);
    cudaGetSymbolAddress((void**)&wihi, g_wihi);
    cudaGetSymbolAddress((void**)&wilo, g_wilo);
    cudaGetSymbolAddress((void**)&wohi, g_wohi);
    cudaGetSymbolAddress((void**)&wolo, g_wolo);
    cudaGetSymbolAddress((void**)&ohi,  g_ohi);
    cudaGetSymbolAddress((void**)&olo,  g_olo);

    // 1) split inputs to bf16 hi/lo
    split_kernel<<<(BB*NN*CC + 255) / 256, 256>>>(x, xhi, xlo, BB*NN*CC);
    split_kernel<<<(3*CC*CC + 255) / 256, 256>>>(w_in, wihi, wilo, 3*CC*CC);
    split_kernel<<<(CC*CC + 255) / 256, 256>>>(w_out, wohi, wolo, CC*CC);

    // 2) QKV projection (writes split q/k/v, q pre-scaled)
    gemm_mma_kernel<<<dim3(24, 64), 256, GEMM_SMEM>>>(
        xhi, xlo, wihi, wilo, b_in, nullptr, 0);

    // 3) tensor-core flash attention
    attn_mma_kernel<<<dim3(8, 128), 256, ATTN_SMEM>>>();

    // 4) out projection
    gemm_mma_kernel<<<dim3(8, 64), 256, GEMM_SMEM>>>(
        ohi, olo, wohi, wolo, b_out, out, 1);
}